// round 1
// baseline (speedup 1.0000x reference)
#include <cuda_runtime.h>
#include <math.h>

#define D 128
#define MAXN 50048

// ---------------- scratch (device globals: allocation-free) ----------------
__device__ float g_dinv[MAXN];                 // deg -> rsqrt(deg)
__device__ float g_sxh[(size_t)MAXN * 256];    // [S@xin | S@h]   (agg target / GEMM1 A)
__device__ float g_P[(size_t)MAXN * 384];      // GEMM1 out: [z_pre | r_pre | xh_part]
__device__ float g_rh[(size_t)MAXN * D];       // r * h          (agg source)
__device__ float g_Sr[(size_t)MAXN * D];       // S @ (r*h)      (agg target / GEMM2 A)
__device__ float g_Q[(size_t)MAXN * D];        // GEMM2 out: (S rh) @ Whh
__device__ float g_z[(size_t)MAXN * D];        // z gate
__device__ float g_Wc[256 * 384];              // combined weight [ [Wxz;Whz] [Wxr;Whr] [Wxh;0] ]

// ---------------- helpers ----------------
__device__ __forceinline__ void red_add_v4(float4* addr, float4 v) {
    asm volatile("red.global.add.v4.f32 [%0], {%1,%2,%3,%4};"
                 :: "l"(addr), "f"(v.x), "f"(v.y), "f"(v.z), "f"(v.w)
                 : "memory");
}
__device__ __forceinline__ float sigmoidf(float x) { return 1.0f / (1.0f + expf(-x)); }

// ---------------- degree / norm ----------------
__global__ void k_deg_init(int n) {
    int i = blockIdx.x * blockDim.x + threadIdx.x;
    if (i < n) g_dinv[i] = 1.0f;  // self-loop weight 1
}
__global__ void k_deg_edges(const int* __restrict__ coli, const float* __restrict__ w, int E) {
    int e = blockIdx.x * blockDim.x + threadIdx.x;
    if (e < E) atomicAdd(&g_dinv[coli[e]], w[e]);
}
__global__ void k_dinv(int n) {
    int i = blockIdx.x * blockDim.x + threadIdx.x;
    if (i < n) {
        float d = g_dinv[i];
        g_dinv[i] = (d > 0.0f) ? rsqrtf(d) : 0.0f;
    }
}

// ---------------- combined weight build ----------------
__global__ void k_build_wc(const float* __restrict__ Wxz, const float* __restrict__ Whz,
                           const float* __restrict__ Wxr, const float* __restrict__ Whr,
                           const float* __restrict__ Wxh) {
    int idx = blockIdx.x * blockDim.x + threadIdx.x;  // 256*384
    if (idx >= 256 * 384) return;
    int k = idx / 384, n = idx % 384;
    int blk = n >> 7, nn = n & 127;
    float v;
    if (blk == 0)      v = (k < 128) ? Wxz[k * 128 + nn] : Whz[(k - 128) * 128 + nn];
    else if (blk == 1) v = (k < 128) ? Wxr[k * 128 + nn] : Whr[(k - 128) * 128 + nn];
    else               v = (k < 128) ? Wxh[k * 128 + nn] : 0.0f;
    g_Wc[k * 384 + n] = v;
}

// ---------------- aggregation: init with self-loop (norm = dinv^2) ----------------
__global__ void k_agg_init256(const float* __restrict__ xin, const float* __restrict__ hi, int n) {
    int idx = blockIdx.x * blockDim.x + threadIdx.x;  // n*64 float4s
    if (idx >= n * 64) return;
    int m = idx >> 6, j = idx & 63;
    float di = g_dinv[m];
    float s = di * di;
    float4 v = (j < 32) ? __ldg((const float4*)xin + (size_t)m * 32 + j)
                        : __ldg((const float4*)hi  + (size_t)m * 32 + (j - 32));
    v.x *= s; v.y *= s; v.z *= s; v.w *= s;
    ((float4*)g_sxh)[(size_t)m * 64 + j] = v;
}

// ---------------- aggregation edge pass: 256-wide ([xin|h] -> g_sxh) ----------------
__global__ void k_agg_edges256(const int* __restrict__ rowi, const int* __restrict__ coli,
                               const float* __restrict__ w,
                               const float* __restrict__ xin, const float* __restrict__ hi,
                               int E) {
    int gw = (blockIdx.x * blockDim.x + threadIdx.x) >> 5;  // warp = edge
    if (gw >= E) return;
    int lane = threadIdx.x & 31;
    int r = __ldg(rowi + gw), c = __ldg(coli + gw);
    float nrm = __ldg(w + gw) * __ldg(g_dinv + r) * __ldg(g_dinv + c);
    float4 a = __ldg((const float4*)xin + (size_t)r * 32 + lane);
    float4 b = __ldg((const float4*)hi  + (size_t)r * 32 + lane);
    a.x *= nrm; a.y *= nrm; a.z *= nrm; a.w *= nrm;
    b.x *= nrm; b.y *= nrm; b.z *= nrm; b.w *= nrm;
    float4* dst = (float4*)g_sxh + (size_t)c * 64;
    red_add_v4(dst + lane, a);
    red_add_v4(dst + 32 + lane, b);
}

// ---------------- aggregation edge pass: 128-wide (g_rh -> g_Sr) ----------------
__global__ void k_agg_edges128(const int* __restrict__ rowi, const int* __restrict__ coli,
                               const float* __restrict__ w, int E) {
    int gw = (blockIdx.x * blockDim.x + threadIdx.x) >> 5;
    if (gw >= E) return;
    int lane = threadIdx.x & 31;
    int r = __ldg(rowi + gw), c = __ldg(coli + gw);
    float nrm = __ldg(w + gw) * __ldg(g_dinv + r) * __ldg(g_dinv + c);
    float4 a = __ldg((const float4*)g_rh + (size_t)r * 32 + lane);
    a.x *= nrm; a.y *= nrm; a.z *= nrm; a.w *= nrm;
    red_add_v4((float4*)g_Sr + (size_t)c * 32 + lane, a);
}

// ---------------- SGEMM: C[M x 128·gridDim.y] += A[M x K] @ B[K x ldB] ----------------
// BM=BN=128, BK=16, 256 threads, 8x8 register tile.
__global__ void __launch_bounds__(256, 2)
k_gemm(const float* __restrict__ A, const float* __restrict__ B, float* __restrict__ C,
       int M, int K, int ldB, int ldC) {
    const int BK = 16;
    __shared__ float As[BK][128];
    __shared__ float Bs[BK][128];
    int tid = threadIdx.x;
    int blockRow = blockIdx.x * 128;
    int colOff = blockIdx.y * 128;

    int tr = (tid / 16) * 8;
    int tc = (tid % 16) * 8;
    float acc[8][8] = {};

    int arow = tid >> 2;          // 0..63
    int acol = (tid & 3) * 4;     // 0,4,8,12
    int brow = tid >> 5;          // 0..7
    int bcol = (tid & 31) * 4;    // 0..124

    for (int k0 = 0; k0 < K; k0 += BK) {
#pragma unroll
        for (int s = 0; s < 2; s++) {
            int m = blockRow + arow + s * 64;
            float4 v = make_float4(0.f, 0.f, 0.f, 0.f);
            if (m < M) v = __ldg((const float4*)(A + (size_t)m * K + k0 + acol));
            As[acol + 0][arow + s * 64] = v.x;
            As[acol + 1][arow + s * 64] = v.y;
            As[acol + 2][arow + s * 64] = v.z;
            As[acol + 3][arow + s * 64] = v.w;
        }
#pragma unroll
        for (int s = 0; s < 2; s++) {
            int k = k0 + brow + s * 8;
            float4 v = __ldg((const float4*)(B + (size_t)k * ldB + colOff + bcol));
            *(float4*)&Bs[brow + s * 8][bcol] = v;
        }
        __syncthreads();
#pragma unroll
        for (int kk = 0; kk < BK; kk++) {
            float ra[8], rb[8];
            *(float4*)&ra[0] = *(float4*)&As[kk][tr];
            *(float4*)&ra[4] = *(float4*)&As[kk][tr + 4];
            *(float4*)&rb[0] = *(float4*)&Bs[kk][tc];
            *(float4*)&rb[4] = *(float4*)&Bs[kk][tc + 4];
#pragma unroll
            for (int i = 0; i < 8; i++)
#pragma unroll
                for (int j = 0; j < 8; j++)
                    acc[i][j] += ra[i] * rb[j];
        }
        __syncthreads();
    }
#pragma unroll
    for (int i = 0; i < 8; i++) {
        int m = blockRow + tr + i;
        if (m < M) {
#pragma unroll
            for (int j = 0; j < 8; j += 4) {
                float4 v = make_float4(acc[i][j], acc[i][j + 1], acc[i][j + 2], acc[i][j + 3]);
                *(float4*)(C + (size_t)m * ldC + colOff + tc + j) = v;
            }
        }
    }
}

// ---------------- gates: z, r, rh, and seed Sr with self-loop term ----------------
__global__ void k_gate(const float* __restrict__ hi,
                       const float* __restrict__ bxz, const float* __restrict__ bhz,
                       const float* __restrict__ bxr, const float* __restrict__ bhr, int n) {
    int idx = blockIdx.x * blockDim.x + threadIdx.x;  // n*32 float4s
    if (idx >= n * 32) return;
    int m = idx >> 5, j = idx & 31;
    const float4* P4 = (const float4*)g_P;
    float4 pz = P4[(size_t)m * 96 + j];
    float4 pr = P4[(size_t)m * 96 + 32 + j];
    float4 b0 = __ldg((const float4*)bxz + j);
    float4 b1 = __ldg((const float4*)bhz + j);
    float4 b2 = __ldg((const float4*)bxr + j);
    float4 b3 = __ldg((const float4*)bhr + j);
    float4 hv = __ldg((const float4*)hi + (size_t)m * 32 + j);
    float di = g_dinv[m];
    float s = di * di;

    float4 z, rh, sr;
    z.x = sigmoidf(pz.x + b0.x + b1.x); z.y = sigmoidf(pz.y + b0.y + b1.y);
    z.z = sigmoidf(pz.z + b0.z + b1.z); z.w = sigmoidf(pz.w + b0.w + b1.w);
    float rx = sigmoidf(pr.x + b2.x + b3.x), ry = sigmoidf(pr.y + b2.y + b3.y);
    float rz = sigmoidf(pr.z + b2.z + b3.z), rw = sigmoidf(pr.w + b2.w + b3.w);
    rh.x = rx * hv.x; rh.y = ry * hv.y; rh.z = rz * hv.z; rh.w = rw * hv.w;
    sr.x = s * rh.x; sr.y = s * rh.y; sr.z = s * rh.z; sr.w = s * rh.w;

    ((float4*)g_z)[(size_t)m * 32 + j] = z;
    ((float4*)g_rh)[(size_t)m * 32 + j] = rh;
    ((float4*)g_Sr)[(size_t)m * 32 + j] = sr;
}

// ---------------- final: ht, ho ----------------
__global__ void k_final(const float* __restrict__ hi,
                        const float* __restrict__ bxh, const float* __restrict__ bhh,
                        float* __restrict__ out, int n) {
    int idx = blockIdx.x * blockDim.x + threadIdx.x;  // n*32 float4s
    if (idx >= n * 32) return;
    int m = idx >> 5, j = idx & 31;
    float4 pxh = ((const float4*)g_P)[(size_t)m * 96 + 64 + j];
    float4 q = ((const float4*)g_Q)[(size_t)m * 32 + j];
    float4 b0 = __ldg((const float4*)bxh + j);
    float4 b1 = __ldg((const float4*)bhh + j);
    float4 zv = ((const float4*)g_z)[(size_t)m * 32 + j];
    float4 hv = __ldg((const float4*)hi + (size_t)m * 32 + j);
    float4 ho;
    float ht;
    ht = tanhf(pxh.x + q.x + b0.x + b1.x); ho.x = zv.x * hv.x + (1.0f - zv.x) * ht;
    ht = tanhf(pxh.y + q.y + b0.y + b1.y); ho.y = zv.y * hv.y + (1.0f - zv.y) * ht;
    ht = tanhf(pxh.z + q.z + b0.z + b1.z); ho.z = zv.z * hv.z + (1.0f - zv.z) * ht;
    ht = tanhf(pxh.w + q.w + b0.w + b1.w); ho.w = zv.w * hv.w + (1.0f - zv.w) * ht;
    ((float4*)out)[(size_t)m * 32 + j] = ho;
}

// ---------------- host ----------------
extern "C" void kernel_launch(void* const* d_in, const int* in_sizes, int n_in,
                              void* d_out, int out_size) {
    const float* x   = (const float*)d_in[0];
    const int*   ei  = (const int*)d_in[1];
    const float* ew  = (const float*)d_in[2];
    const float* h   = (const float*)d_in[3];
    const float* Wxz = (const float*)d_in[4];  const float* bxz = (const float*)d_in[5];
    const float* Whz = (const float*)d_in[6];  const float* bhz = (const float*)d_in[7];
    const float* Wxr = (const float*)d_in[8];  const float* bxr = (const float*)d_in[9];
    const float* Whr = (const float*)d_in[10]; const float* bhr = (const float*)d_in[11];
    const float* Wxh = (const float*)d_in[12]; const float* bxh = (const float*)d_in[13];
    const float* Whh = (const float*)d_in[14]; const float* bhh = (const float*)d_in[15];
    float* out = (float*)d_out;

    int N = in_sizes[0] / D;
    int E = in_sizes[2];
    int L = in_sizes[5] / D;

    const int* rowi = ei;       // source
    const int* coli = ei + E;   // target

    float *p_sxh, *p_P, *p_Wc, *p_Sr, *p_Q;
    cudaGetSymbolAddress((void**)&p_sxh, g_sxh);
    cudaGetSymbolAddress((void**)&p_P,   g_P);
    cudaGetSymbolAddress((void**)&p_Wc,  g_Wc);
    cudaGetSymbolAddress((void**)&p_Sr,  g_Sr);
    cudaGetSymbolAddress((void**)&p_Q,   g_Q);

    // degree / normalization (shared by all convs)
    k_deg_init<<<(N + 255) / 256, 256>>>(N);
    k_deg_edges<<<(E + 255) / 256, 256>>>(coli, ew, E);
    k_dinv<<<(N + 255) / 256, 256>>>(N);

    int eblocks = (E * 32 + 255) / 256;  // warp per edge

    for (int i = 0; i < L; i++) {
        const float* xin = (i == 0) ? x : out + (size_t)(i - 1) * N * D;
        const float* hi = h + (size_t)i * N * D;

        k_build_wc<<<(256 * 384 + 255) / 256, 256>>>(Wxz + (size_t)i * D * D, Whz + (size_t)i * D * D,
                                                     Wxr + (size_t)i * D * D, Whr + (size_t)i * D * D,
                                                     Wxh + (size_t)i * D * D);
        k_agg_init256<<<(N * 64 + 255) / 256, 256>>>(xin, hi, N);
        k_agg_edges256<<<eblocks, 256>>>(rowi, coli, ew, xin, hi, E);
        k_gemm<<<dim3((N + 127) / 128, 3), 256>>>(p_sxh, p_Wc, p_P, N, 256, 384, 384);
        k_gate<<<(N * 32 + 255) / 256, 256>>>(hi, bxz + i * D, bhz + i * D, bxr + i * D, bhr + i * D, N);
        k_agg_edges128<<<eblocks, 256>>>(rowi, coli, ew, E);
        k_gemm<<<dim3((N + 127) / 128, 1), 256>>>(p_Sr, Whh + (size_t)i * D * D, p_Q, N, 128, 128, 128);
        k_final<<<(N * 32 + 255) / 256, 256>>>(hi, bxh + i * D, bhh + i * D, out + (size_t)i * N * D, N);
    }
}

// round 3
// speedup vs baseline: 1.0596x; 1.0596x over previous
#include <cuda_runtime.h>
#include <cuda_bf16.h>
#include <mma.h>
#include <math.h>
#include <stdint.h>

using namespace nvcuda;

#define D 128
#define MAXN 50048
#define MAXE 1700000

// ---------------- scratch (device globals: allocation-free) ----------------
__device__ float g_dinv[MAXN];                 // deg -> rsqrt(deg)
__device__ float g_enorm[MAXE];                // per-edge norm
__device__ float g_sxh[(size_t)MAXN * 256];    // [S@xin | S@h]   (agg target / GEMM1 A)
__device__ float g_P[(size_t)MAXN * 384];      // GEMM1 out: [z_pre | r_pre | xh_part]
__device__ float g_rh[(size_t)MAXN * D];       // r * h          (agg source)
__device__ float g_Sr[(size_t)MAXN * D];       // S @ (r*h)      (agg target / GEMM2 A)
__device__ float g_Q[(size_t)MAXN * D];        // GEMM2 out
__device__ float g_z[(size_t)MAXN * D];        // z gate
__device__ __nv_bfloat16 g_Wt1hi[384 * 256];   // GEMM1 B (n-major, split)
__device__ __nv_bfloat16 g_Wt1lo[384 * 256];
__device__ __nv_bfloat16 g_Wt2hi[128 * 128];   // GEMM2 B (n-major, split)
__device__ __nv_bfloat16 g_Wt2lo[128 * 128];

// ---------------- helpers ----------------
__device__ __forceinline__ void red_add_v4(float4* addr, float4 v) {
    asm volatile("red.global.add.v4.f32 [%0], {%1,%2,%3,%4};"
                 :: "l"(addr), "f"(v.x), "f"(v.y), "f"(v.z), "f"(v.w) : "memory");
}
__device__ __forceinline__ float sigmoidf(float x) { return 1.0f / (1.0f + expf(-x)); }

// ---------------- degree / norm ----------------
__global__ void k_deg_init(int n) {
    int i = blockIdx.x * blockDim.x + threadIdx.x;
    if (i < n) g_dinv[i] = 1.0f;
}
__global__ void k_deg_edges(const int* __restrict__ coli, const float* __restrict__ w, int E) {
    int e = blockIdx.x * blockDim.x + threadIdx.x;
    if (e < E) atomicAdd(&g_dinv[coli[e]], w[e]);
}
__global__ void k_dinv(int n) {
    int i = blockIdx.x * blockDim.x + threadIdx.x;
    if (i < n) {
        float d = g_dinv[i];
        g_dinv[i] = (d > 0.0f) ? rsqrtf(d) : 0.0f;
    }
}
__global__ void k_enorm(const int* __restrict__ rowi, const int* __restrict__ coli,
                        const float* __restrict__ w, int E) {
    int e = blockIdx.x * blockDim.x + threadIdx.x;
    if (e < E) g_enorm[e] = w[e] * __ldg(g_dinv + rowi[e]) * __ldg(g_dinv + coli[e]);
}

// ---------------- weight build (transposed + bf16 split) ----------------
__global__ void k_build_wt1(const float* __restrict__ Wxz, const float* __restrict__ Whz,
                            const float* __restrict__ Wxr, const float* __restrict__ Whr,
                            const float* __restrict__ Wxh) {
    int idx = blockIdx.x * blockDim.x + threadIdx.x;  // 384*256, n-major
    if (idx >= 384 * 256) return;
    int n = idx / 256, k = idx % 256;
    int blk = n >> 7, nn = n & 127;
    float v;
    if (blk == 0)      v = (k < 128) ? Wxz[k * 128 + nn] : Whz[(k - 128) * 128 + nn];
    else if (blk == 1) v = (k < 128) ? Wxr[k * 128 + nn] : Whr[(k - 128) * 128 + nn];
    else               v = (k < 128) ? Wxh[k * 128 + nn] : 0.0f;
    __nv_bfloat16 hi = __float2bfloat16(v);
    g_Wt1hi[idx] = hi;
    g_Wt1lo[idx] = __float2bfloat16(v - __bfloat162float(hi));
}
__global__ void k_build_wt2(const float* __restrict__ Whh) {
    int idx = blockIdx.x * blockDim.x + threadIdx.x;  // 128*128, n-major
    if (idx >= 128 * 128) return;
    int n = idx / 128, k = idx % 128;
    float v = Whh[k * 128 + n];
    __nv_bfloat16 hi = __float2bfloat16(v);
    g_Wt2hi[idx] = hi;
    g_Wt2lo[idx] = __float2bfloat16(v - __bfloat162float(hi));
}

// ---------------- aggregation ----------------
__global__ void k_agg_init256(const float* __restrict__ xin, const float* __restrict__ hi, int n) {
    int idx = blockIdx.x * blockDim.x + threadIdx.x;
    if (idx >= n * 64) return;
    int m = idx >> 6, j = idx & 63;
    float di = g_dinv[m];
    float s = di * di;
    float4 v = (j < 32) ? __ldg((const float4*)xin + (size_t)m * 32 + j)
                        : __ldg((const float4*)hi  + (size_t)m * 32 + (j - 32));
    v.x *= s; v.y *= s; v.z *= s; v.w *= s;
    ((float4*)g_sxh)[(size_t)m * 64 + j] = v;
}
__global__ void k_agg_edges256(const int* __restrict__ rowi, const int* __restrict__ coli,
                               const float* __restrict__ xin, const float* __restrict__ hi,
                               int E) {
    int gw = (blockIdx.x * blockDim.x + threadIdx.x) >> 5;
    if (gw >= E) return;
    int lane = threadIdx.x & 31;
    int r = __ldg(rowi + gw), c = __ldg(coli + gw);
    float nrm = __ldg(g_enorm + gw);
    float4 a = __ldg((const float4*)xin + (size_t)r * 32 + lane);
    float4 b = __ldg((const float4*)hi  + (size_t)r * 32 + lane);
    a.x *= nrm; a.y *= nrm; a.z *= nrm; a.w *= nrm;
    b.x *= nrm; b.y *= nrm; b.z *= nrm; b.w *= nrm;
    float4* dst = (float4*)g_sxh + (size_t)c * 64;
    red_add_v4(dst + lane, a);
    red_add_v4(dst + 32 + lane, b);
}
__global__ void k_agg_edges128(const int* __restrict__ rowi, const int* __restrict__ coli, int E) {
    int gw = (blockIdx.x * blockDim.x + threadIdx.x) >> 5;
    if (gw >= E) return;
    int lane = threadIdx.x & 31;
    int r = __ldg(rowi + gw), c = __ldg(coli + gw);
    float nrm = __ldg(g_enorm + gw);
    float4 a = __ldg((const float4*)g_rh + (size_t)r * 32 + lane);
    a.x *= nrm; a.y *= nrm; a.z *= nrm; a.w *= nrm;
    red_add_v4((float4*)g_Sr + (size_t)c * 32 + lane, a);
}

// ---------------- WMMA split-bf16 GEMM ----------------
// C[128 x 64 tile] = A[fp32, M x K] @ B^T, B given n-major [NB x K] bf16 hi/lo.
// 3-pass emulation: Ahi*Bhi + Ahi*Blo + Alo*Bhi with fp32 accumulators.
// Grid: (ceil(M/128), NB/64). 256 threads = 8 warps (4M x 2N), warp tile 32x32.
__global__ void __launch_bounds__(256, 1)
k_wgemm(const float* __restrict__ A, const __nv_bfloat16* __restrict__ Bhi,
        const __nv_bfloat16* __restrict__ Blo, float* __restrict__ C,
        int M, int K, int ldC) {
    extern __shared__ char smem[];
    const int tid = threadIdx.x;
    const int blockRow = blockIdx.x * 128;
    const int n0 = blockIdx.y * 64;
    const int ldS = K + 16;  // padded leading dim (elements)

    __nv_bfloat16* Ahi = (__nv_bfloat16*)smem;                     // [128][ldS]
    __nv_bfloat16* Alo = Ahi + 128 * ldS;
    __nv_bfloat16* Bh  = Alo + 128 * ldS;                          // [64][ldS] n-major
    __nv_bfloat16* Bl  = Bh + 64 * ldS;

    // ---- load A fp32 -> split bf16 hi/lo into SMEM ----
    {
        const int K4 = K >> 2;
        for (int idx = tid; idx < 128 * K4; idx += 256) {
            int r = idx / K4, c = (idx % K4) * 4;
            float4 v = __ldg((const float4*)(A + (size_t)(blockRow + r) * K + c));
            __nv_bfloat16 h0 = __float2bfloat16(v.x), h1 = __float2bfloat16(v.y);
            __nv_bfloat16 h2 = __float2bfloat16(v.z), h3 = __float2bfloat16(v.w);
            __nv_bfloat16 l0 = __float2bfloat16(v.x - __bfloat162float(h0));
            __nv_bfloat16 l1 = __float2bfloat16(v.y - __bfloat162float(h1));
            __nv_bfloat16 l2 = __float2bfloat16(v.z - __bfloat162float(h2));
            __nv_bfloat16 l3 = __float2bfloat16(v.w - __bfloat162float(h3));
            uint32_t hw0 = ((uint32_t)__bfloat16_as_ushort(h1) << 16) | __bfloat16_as_ushort(h0);
            uint32_t hw1 = ((uint32_t)__bfloat16_as_ushort(h3) << 16) | __bfloat16_as_ushort(h2);
            uint32_t lw0 = ((uint32_t)__bfloat16_as_ushort(l1) << 16) | __bfloat16_as_ushort(l0);
            uint32_t lw1 = ((uint32_t)__bfloat16_as_ushort(l3) << 16) | __bfloat16_as_ushort(l2);
            *(uint2*)(Ahi + (size_t)r * ldS + c) = make_uint2(hw0, hw1);
            *(uint2*)(Alo + (size_t)r * ldS + c) = make_uint2(lw0, lw1);
        }
    }
    // ---- load B bf16 hi/lo (n-major) into SMEM ----
    {
        const int K8 = K >> 3;
        for (int idx = tid; idx < 64 * K8; idx += 256) {
            int n = idx / K8, c = (idx % K8) * 8;
            uint4 vh = __ldg((const uint4*)(Bhi + (size_t)(n0 + n) * K + c));
            uint4 vl = __ldg((const uint4*)(Blo + (size_t)(n0 + n) * K + c));
            *(uint4*)(Bh + (size_t)n * ldS + c) = vh;
            *(uint4*)(Bl + (size_t)n * ldS + c) = vl;
        }
    }
    __syncthreads();

    const int warpId = tid >> 5;
    const int wm = warpId & 3;   // 0..3 -> M
    const int wn = warpId >> 2;  // 0..1 -> N
    const int row0 = wm * 32;
    const int col0 = wn * 32;

    wmma::fragment<wmma::accumulator, 16, 16, 16, float> acc[2][2];
#pragma unroll
    for (int i = 0; i < 2; i++)
#pragma unroll
        for (int j = 0; j < 2; j++) wmma::fill_fragment(acc[i][j], 0.0f);

    for (int k0 = 0; k0 < K; k0 += 16) {
        wmma::fragment<wmma::matrix_a, 16, 16, 16, __nv_bfloat16, wmma::row_major> ah[2], al[2];
        wmma::fragment<wmma::matrix_b, 16, 16, 16, __nv_bfloat16, wmma::col_major> bh[2], bl[2];
#pragma unroll
        for (int i = 0; i < 2; i++) {
            wmma::load_matrix_sync(ah[i], Ahi + (size_t)(row0 + i * 16) * ldS + k0, ldS);
            wmma::load_matrix_sync(al[i], Alo + (size_t)(row0 + i * 16) * ldS + k0, ldS);
        }
#pragma unroll
        for (int j = 0; j < 2; j++) {
            wmma::load_matrix_sync(bh[j], Bh + (size_t)(col0 + j * 16) * ldS + k0, ldS);
            wmma::load_matrix_sync(bl[j], Bl + (size_t)(col0 + j * 16) * ldS + k0, ldS);
        }
#pragma unroll
        for (int i = 0; i < 2; i++)
#pragma unroll
            for (int j = 0; j < 2; j++) {
                wmma::mma_sync(acc[i][j], ah[i], bh[j], acc[i][j]);
                wmma::mma_sync(acc[i][j], ah[i], bl[j], acc[i][j]);
                wmma::mma_sync(acc[i][j], al[i], bh[j], acc[i][j]);
            }
    }

#pragma unroll
    for (int i = 0; i < 2; i++)
#pragma unroll
        for (int j = 0; j < 2; j++) {
            float* cp = C + (size_t)(blockRow + row0 + i * 16) * ldC + n0 + col0 + j * 16;
            wmma::store_matrix_sync(cp, acc[i][j], ldC, wmma::mem_row_major);
        }
}

// ---------------- gates ----------------
__global__ void k_gate(const float* __restrict__ hi,
                       const float* __restrict__ bxz, const float* __restrict__ bhz,
                       const float* __restrict__ bxr, const float* __restrict__ bhr, int n) {
    int idx = blockIdx.x * blockDim.x + threadIdx.x;
    if (idx >= n * 32) return;
    int m = idx >> 5, j = idx & 31;
    const float4* P4 = (const float4*)g_P;
    float4 pz = P4[(size_t)m * 96 + j];
    float4 pr = P4[(size_t)m * 96 + 32 + j];
    float4 b0 = __ldg((const float4*)bxz + j);
    float4 b1 = __ldg((const float4*)bhz + j);
    float4 b2 = __ldg((const float4*)bxr + j);
    float4 b3 = __ldg((const float4*)bhr + j);
    float4 hv = __ldg((const float4*)hi + (size_t)m * 32 + j);
    float di = g_dinv[m];
    float s = di * di;

    float4 z, rh, sr;
    z.x = sigmoidf(pz.x + b0.x + b1.x); z.y = sigmoidf(pz.y + b0.y + b1.y);
    z.z = sigmoidf(pz.z + b0.z + b1.z); z.w = sigmoidf(pz.w + b0.w + b1.w);
    float rx = sigmoidf(pr.x + b2.x + b3.x), ry = sigmoidf(pr.y + b2.y + b3.y);
    float rz = sigmoidf(pr.z + b2.z + b3.z), rw = sigmoidf(pr.w + b2.w + b3.w);
    rh.x = rx * hv.x; rh.y = ry * hv.y; rh.z = rz * hv.z; rh.w = rw * hv.w;
    sr.x = s * rh.x; sr.y = s * rh.y; sr.z = s * rh.z; sr.w = s * rh.w;

    ((float4*)g_z)[(size_t)m * 32 + j] = z;
    ((float4*)g_rh)[(size_t)m * 32 + j] = rh;
    ((float4*)g_Sr)[(size_t)m * 32 + j] = sr;
}

// ---------------- final ----------------
__global__ void k_final(const float* __restrict__ hi,
                        const float* __restrict__ bxh, const float* __restrict__ bhh,
                        float* __restrict__ out, int n) {
    int idx = blockIdx.x * blockDim.x + threadIdx.x;
    if (idx >= n * 32) return;
    int m = idx >> 5, j = idx & 31;
    float4 pxh = ((const float4*)g_P)[(size_t)m * 96 + 64 + j];
    float4 q = ((const float4*)g_Q)[(size_t)m * 32 + j];
    float4 b0 = __ldg((const float4*)bxh + j);
    float4 b1 = __ldg((const float4*)bhh + j);
    float4 zv = ((const float4*)g_z)[(size_t)m * 32 + j];
    float4 hv = __ldg((const float4*)hi + (size_t)m * 32 + j);
    float4 ho;
    float ht;
    ht = tanhf(pxh.x + q.x + b0.x + b1.x); ho.x = zv.x * hv.x + (1.0f - zv.x) * ht;
    ht = tanhf(pxh.y + q.y + b0.y + b1.y); ho.y = zv.y * hv.y + (1.0f - zv.y) * ht;
    ht = tanhf(pxh.z + q.z + b0.z + b1.z); ho.z = zv.z * hv.z + (1.0f - zv.z) * ht;
    ht = tanhf(pxh.w + q.w + b0.w + b1.w); ho.w = zv.w * hv.w + (1.0f - zv.w) * ht;
    ((float4*)out)[(size_t)m * 32 + j] = ho;
}

// ---------------- host ----------------
extern "C" void kernel_launch(void* const* d_in, const int* in_sizes, int n_in,
                              void* d_out, int out_size) {
    const float* x   = (const float*)d_in[0];
    const int*   ei  = (const int*)d_in[1];
    const float* ew  = (const float*)d_in[2];
    const float* h   = (const float*)d_in[3];
    const float* Wxz = (const float*)d_in[4];  const float* bxz = (const float*)d_in[5];
    const float* Whz = (const float*)d_in[6];  const float* bhz = (const float*)d_in[7];
    const float* Wxr = (const float*)d_in[8];  const float* bxr = (const float*)d_in[9];
    const float* Whr = (const float*)d_in[10]; const float* bhr = (const float*)d_in[11];
    const float* Wxh = (const float*)d_in[12]; const float* bxh = (const float*)d_in[13];
    const float* Whh = (const float*)d_in[14]; const float* bhh = (const float*)d_in[15];
    float* out = (float*)d_out;

    int N = in_sizes[0] / D;
    int E = in_sizes[2];
    int L = in_sizes[5] / D;

    const int* rowi = ei;
    const int* coli = ei + E;

    float *p_sxh, *p_P, *p_Sr, *p_Q;
    __nv_bfloat16 *p_w1h, *p_w1l, *p_w2h, *p_w2l;
    cudaGetSymbolAddress((void**)&p_sxh, g_sxh);
    cudaGetSymbolAddress((void**)&p_P,   g_P);
    cudaGetSymbolAddress((void**)&p_Sr,  g_Sr);
    cudaGetSymbolAddress((void**)&p_Q,   g_Q);
    cudaGetSymbolAddress((void**)&p_w1h, g_Wt1hi);
    cudaGetSymbolAddress((void**)&p_w1l, g_Wt1lo);
    cudaGetSymbolAddress((void**)&p_w2h, g_Wt2hi);
    cudaGetSymbolAddress((void**)&p_w2l, g_Wt2lo);

    // dynamic smem: 2 * (128 + 64) * (K + 16) * 2 bytes
    int smem1 = 2 * (128 + 64) * (256 + 16) * 2;  // 208,896 (K=256)
    int smem2 = 2 * (128 + 64) * (128 + 16) * 2;  // 110,592 (K=128)
    cudaFuncSetAttribute(k_wgemm, cudaFuncAttributeMaxDynamicSharedMemorySize, smem1);

    // degree / normalization (shared by all convs)
    k_deg_init<<<(N + 255) / 256, 256>>>(N);
    k_deg_edges<<<(E + 255) / 256, 256>>>(coli, ew, E);
    k_dinv<<<(N + 255) / 256, 256>>>(N);
    k_enorm<<<(E + 255) / 256, 256>>>(rowi, coli, ew, E);

    int eblocks = (E * 32 + 255) / 256;
    int mtiles = (N + 127) / 128;

    for (int i = 0; i < L; i++) {
        const float* xin = (i == 0) ? x : out + (size_t)(i - 1) * N * D;
        const float* hi = h + (size_t)i * N * D;

        k_build_wt1<<<(384 * 256 + 255) / 256, 256>>>(Wxz + (size_t)i * D * D, Whz + (size_t)i * D * D,
                                                      Wxr + (size_t)i * D * D, Whr + (size_t)i * D * D,
                                                      Wxh + (size_t)i * D * D);
        k_build_wt2<<<(128 * 128 + 255) / 256, 256>>>(Whh + (size_t)i * D * D);
        k_agg_init256<<<(N * 64 + 255) / 256, 256>>>(xin, hi, N);
        k_agg_edges256<<<eblocks, 256>>>(rowi, coli, xin, hi, E);
        k_wgemm<<<dim3(mtiles, 6), 256, smem1>>>(p_sxh, p_w1h, p_w1l, p_P, N, 256, 384);
        k_gate<<<(N * 32 + 255) / 256, 256>>>(hi, bxz + i * D, bhz + i * D, bxr + i * D, bhr + i * D, N);
        k_agg_edges128<<<eblocks, 256>>>(rowi, coli, E);
        k_wgemm<<<dim3(mtiles, 2), 256, smem2>>>(p_Sr, p_w2h, p_w2l, p_Q, N, 128, 128);
        k_final<<<(N * 32 + 255) / 256, 256>>>(hi, bxh + i * D, bhh + i * D, out + (size_t)i * N * D, N);
    }
}

// round 4
// speedup vs baseline: 1.7077x; 1.6116x over previous
#include <cuda_runtime.h>
#include <cuda_bf16.h>
#include <mma.h>
#include <math.h>
#include <stdint.h>

using namespace nvcuda;

#define D 128
#define MAXN 50048
#define MAXE 1700000

// ---------------- scratch (device globals: allocation-free) ----------------
__device__ float g_dinv[MAXN];                 // deg -> rsqrt(deg)
__device__ int   g_cnt[MAXN];                  // in-degree histogram
__device__ int   g_off[MAXN + 1];              // CSR offsets
__device__ int   g_cur[MAXN];                  // placement cursors
__device__ int2  g_srt[MAXE];                  // packed (row, norm) per edge, grouped by col
__device__ float g_sxh[(size_t)MAXN * 256];    // [S@xin | S@h]   (GEMM1 A)
__device__ float g_P[(size_t)MAXN * 384];      // GEMM1 out: [z_pre | r_pre | xh_part]
__device__ float g_rh[(size_t)MAXN * D];       // r * h
__device__ float g_Sr[(size_t)MAXN * D];       // S @ (r*h)      (GEMM2 A)
__device__ float g_Q[(size_t)MAXN * D];        // GEMM2 out
__device__ float g_z[(size_t)MAXN * D];        // z gate
__device__ __nv_bfloat16 g_Wt1hi[384 * 256];   // GEMM1 B (n-major, split)
__device__ __nv_bfloat16 g_Wt1lo[384 * 256];
__device__ __nv_bfloat16 g_Wt2hi[128 * 128];   // GEMM2 B (n-major, split)
__device__ __nv_bfloat16 g_Wt2lo[128 * 128];

__device__ __forceinline__ float sigmoidf(float x) { return 1.0f / (1.0f + expf(-x)); }

// ---------------- degree / norm ----------------
__global__ void k_deg_init(int n) {
    int i = blockIdx.x * blockDim.x + threadIdx.x;
    if (i < n) { g_dinv[i] = 1.0f; g_cnt[i] = 0; }
}
__global__ void k_deg_edges(const int* __restrict__ coli, const float* __restrict__ w, int E) {
    int e = blockIdx.x * blockDim.x + threadIdx.x;
    if (e < E) {
        int c = coli[e];
        atomicAdd(&g_dinv[c], w[e]);
        atomicAdd(&g_cnt[c], 1);
    }
}
__global__ void k_dinv(int n) {
    int i = blockIdx.x * blockDim.x + threadIdx.x;
    if (i < n) {
        float d = g_dinv[i];
        g_dinv[i] = (d > 0.0f) ? rsqrtf(d) : 0.0f;
    }
}

// ---------------- single-block scan: g_off (exclusive+1), g_cur ----------------
__global__ void k_scan(int n) {
    __shared__ int sm[1024];
    __shared__ int carry;
    if (threadIdx.x == 0) { carry = 0; g_off[0] = 0; }
    __syncthreads();
    for (int base = 0; base < n; base += 1024) {
        int i = base + threadIdx.x;
        int v = (i < n) ? g_cnt[i] : 0;
        sm[threadIdx.x] = v;
        __syncthreads();
        for (int ofs = 1; ofs < 1024; ofs <<= 1) {
            int t = (threadIdx.x >= ofs) ? sm[threadIdx.x - ofs] : 0;
            __syncthreads();
            sm[threadIdx.x] += t;
            __syncthreads();
        }
        if (i < n) {
            int inc = sm[threadIdx.x];
            g_off[i + 1] = inc + carry;
            g_cur[i] = inc - v + carry;
        }
        __syncthreads();
        if (threadIdx.x == 0) carry += sm[1023];
        __syncthreads();
    }
}

// ---------------- placement scatter: (row, norm) grouped by col ----------------
__global__ void k_place(const int* __restrict__ rowi, const int* __restrict__ coli,
                        const float* __restrict__ w, int E) {
    int e = blockIdx.x * blockDim.x + threadIdx.x;
    if (e >= E) return;
    int r = rowi[e], c = coli[e];
    float nrm = w[e] * __ldg(g_dinv + r) * __ldg(g_dinv + c);
    int pos = atomicAdd(&g_cur[c], 1);
    g_srt[pos] = make_int2(r, __float_as_int(nrm));
}

// ---------------- weight build (transposed + bf16 split) ----------------
__global__ void k_build_wt1(const float* __restrict__ Wxz, const float* __restrict__ Whz,
                            const float* __restrict__ Wxr, const float* __restrict__ Whr,
                            const float* __restrict__ Wxh) {
    int idx = blockIdx.x * blockDim.x + threadIdx.x;  // 384*256, n-major
    if (idx >= 384 * 256) return;
    int n = idx / 256, k = idx % 256;
    int blk = n >> 7, nn = n & 127;
    float v;
    if (blk == 0)      v = (k < 128) ? Wxz[k * 128 + nn] : Whz[(k - 128) * 128 + nn];
    else if (blk == 1) v = (k < 128) ? Wxr[k * 128 + nn] : Whr[(k - 128) * 128 + nn];
    else               v = (k < 128) ? Wxh[k * 128 + nn] : 0.0f;
    __nv_bfloat16 hi = __float2bfloat16(v);
    g_Wt1hi[idx] = hi;
    g_Wt1lo[idx] = __float2bfloat16(v - __bfloat162float(hi));
}
__global__ void k_build_wt2(const float* __restrict__ Whh) {
    int idx = blockIdx.x * blockDim.x + threadIdx.x;  // 128*128, n-major
    if (idx >= 128 * 128) return;
    int n = idx / 128, k = idx % 128;
    float v = Whh[k * 128 + n];
    __nv_bfloat16 hi = __float2bfloat16(v);
    g_Wt2hi[idx] = hi;
    g_Wt2lo[idx] = __float2bfloat16(v - __bfloat162float(hi));
}

// ---------------- CSR gather: 256-wide ([x|h] -> g_sxh), warp per node ----------------
__global__ void __launch_bounds__(256)
k_csr256(const float* __restrict__ xin, const float* __restrict__ hi, int n) {
    int node = (blockIdx.x * blockDim.x + threadIdx.x) >> 5;
    if (node >= n) return;
    int lane = threadIdx.x & 31;
    const float4* x4 = (const float4*)xin;
    const float4* h4 = (const float4*)hi;
    float di = __ldg(g_dinv + node);
    float s = di * di;
    float4 ax = __ldg(x4 + (size_t)node * 32 + lane);
    float4 ah = __ldg(h4 + (size_t)node * 32 + lane);
    ax.x *= s; ax.y *= s; ax.z *= s; ax.w *= s;
    ah.x *= s; ah.y *= s; ah.z *= s; ah.w *= s;
    int e0 = __ldg(g_off + node), e1 = __ldg(g_off + node + 1);
#pragma unroll 4
    for (int e = e0; e < e1; e++) {
        int2 p = __ldg(g_srt + e);
        float nrm = __int_as_float(p.y);
        float4 vx = __ldg(x4 + (size_t)p.x * 32 + lane);
        float4 vh = __ldg(h4 + (size_t)p.x * 32 + lane);
        ax.x += nrm * vx.x; ax.y += nrm * vx.y; ax.z += nrm * vx.z; ax.w += nrm * vx.w;
        ah.x += nrm * vh.x; ah.y += nrm * vh.y; ah.z += nrm * vh.z; ah.w += nrm * vh.w;
    }
    float4* dst = (float4*)g_sxh + (size_t)node * 64;
    dst[lane] = ax;
    dst[32 + lane] = ah;
}

// ---------------- CSR gather: 128-wide (g_rh -> g_Sr), warp per node ----------------
__global__ void __launch_bounds__(256)
k_csr128(int n) {
    int node = (blockIdx.x * blockDim.x + threadIdx.x) >> 5;
    if (node >= n) return;
    int lane = threadIdx.x & 31;
    const float4* r4 = (const float4*)g_rh;
    float di = __ldg(g_dinv + node);
    float s = di * di;
    float4 acc = r4[(size_t)node * 32 + lane];
    acc.x *= s; acc.y *= s; acc.z *= s; acc.w *= s;
    int e0 = __ldg(g_off + node), e1 = __ldg(g_off + node + 1);
#pragma unroll 4
    for (int e = e0; e < e1; e++) {
        int2 p = __ldg(g_srt + e);
        float nrm = __int_as_float(p.y);
        float4 v = __ldg(r4 + (size_t)p.x * 32 + lane);
        acc.x += nrm * v.x; acc.y += nrm * v.y; acc.z += nrm * v.z; acc.w += nrm * v.w;
    }
    ((float4*)g_Sr)[(size_t)node * 32 + lane] = acc;
}

// ---------------- WMMA split-bf16 GEMM ----------------
// C[128 x 64 tile] = A[fp32, M x K] @ B^T, B n-major [NB x K] bf16 hi/lo.
// 3-pass: Ahi*Bhi + Ahi*Blo + Alo*Bhi, fp32 accumulate.
__global__ void __launch_bounds__(256, 1)
k_wgemm(const float* __restrict__ A, const __nv_bfloat16* __restrict__ Bhi,
        const __nv_bfloat16* __restrict__ Blo, float* __restrict__ C,
        int M, int K, int ldC) {
    extern __shared__ char smem[];
    const int tid = threadIdx.x;
    const int blockRow = blockIdx.x * 128;
    const int n0 = blockIdx.y * 64;
    const int ldS = K + 16;

    __nv_bfloat16* Ahi = (__nv_bfloat16*)smem;
    __nv_bfloat16* Alo = Ahi + 128 * ldS;
    __nv_bfloat16* Bh  = Alo + 128 * ldS;
    __nv_bfloat16* Bl  = Bh + 64 * ldS;

    {
        const int K4 = K >> 2;
        for (int idx = tid; idx < 128 * K4; idx += 256) {
            int r = idx / K4, c = (idx % K4) * 4;
            float4 v = __ldg((const float4*)(A + (size_t)(blockRow + r) * K + c));
            __nv_bfloat16 h0 = __float2bfloat16(v.x), h1 = __float2bfloat16(v.y);
            __nv_bfloat16 h2 = __float2bfloat16(v.z), h3 = __float2bfloat16(v.w);
            __nv_bfloat16 l0 = __float2bfloat16(v.x - __bfloat162float(h0));
            __nv_bfloat16 l1 = __float2bfloat16(v.y - __bfloat162float(h1));
            __nv_bfloat16 l2 = __float2bfloat16(v.z - __bfloat162float(h2));
            __nv_bfloat16 l3 = __float2bfloat16(v.w - __bfloat162float(h3));
            uint32_t hw0 = ((uint32_t)__bfloat16_as_ushort(h1) << 16) | __bfloat16_as_ushort(h0);
            uint32_t hw1 = ((uint32_t)__bfloat16_as_ushort(h3) << 16) | __bfloat16_as_ushort(h2);
            uint32_t lw0 = ((uint32_t)__bfloat16_as_ushort(l1) << 16) | __bfloat16_as_ushort(l0);
            uint32_t lw1 = ((uint32_t)__bfloat16_as_ushort(l3) << 16) | __bfloat16_as_ushort(l2);
            *(uint2*)(Ahi + (size_t)r * ldS + c) = make_uint2(hw0, hw1);
            *(uint2*)(Alo + (size_t)r * ldS + c) = make_uint2(lw0, lw1);
        }
    }
    {
        const int K8 = K >> 3;
        for (int idx = tid; idx < 64 * K8; idx += 256) {
            int n = idx / K8, c = (idx % K8) * 8;
            uint4 vh = __ldg((const uint4*)(Bhi + (size_t)(n0 + n) * K + c));
            uint4 vl = __ldg((const uint4*)(Blo + (size_t)(n0 + n) * K + c));
            *(uint4*)(Bh + (size_t)n * ldS + c) = vh;
            *(uint4*)(Bl + (size_t)n * ldS + c) = vl;
        }
    }
    __syncthreads();

    const int warpId = tid >> 5;
    const int wm = warpId & 3;
    const int wn = warpId >> 2;
    const int row0 = wm * 32;
    const int col0 = wn * 32;

    wmma::fragment<wmma::accumulator, 16, 16, 16, float> acc[2][2];
#pragma unroll
    for (int i = 0; i < 2; i++)
#pragma unroll
        for (int j = 0; j < 2; j++) wmma::fill_fragment(acc[i][j], 0.0f);

    for (int k0 = 0; k0 < K; k0 += 16) {
        wmma::fragment<wmma::matrix_a, 16, 16, 16, __nv_bfloat16, wmma::row_major> ah[2], al[2];
        wmma::fragment<wmma::matrix_b, 16, 16, 16, __nv_bfloat16, wmma::col_major> bh[2], bl[2];
#pragma unroll
        for (int i = 0; i < 2; i++) {
            wmma::load_matrix_sync(ah[i], Ahi + (size_t)(row0 + i * 16) * ldS + k0, ldS);
            wmma::load_matrix_sync(al[i], Alo + (size_t)(row0 + i * 16) * ldS + k0, ldS);
        }
#pragma unroll
        for (int j = 0; j < 2; j++) {
            wmma::load_matrix_sync(bh[j], Bh + (size_t)(col0 + j * 16) * ldS + k0, ldS);
            wmma::load_matrix_sync(bl[j], Bl + (size_t)(col0 + j * 16) * ldS + k0, ldS);
        }
#pragma unroll
        for (int i = 0; i < 2; i++)
#pragma unroll
            for (int j = 0; j < 2; j++) {
                wmma::mma_sync(acc[i][j], ah[i], bh[j], acc[i][j]);
                wmma::mma_sync(acc[i][j], ah[i], bl[j], acc[i][j]);
                wmma::mma_sync(acc[i][j], al[i], bh[j], acc[i][j]);
            }
    }

#pragma unroll
    for (int i = 0; i < 2; i++)
#pragma unroll
        for (int j = 0; j < 2; j++) {
            float* cp = C + (size_t)(blockRow + row0 + i * 16) * ldC + n0 + col0 + j * 16;
            wmma::store_matrix_sync(cp, acc[i][j], ldC, wmma::mem_row_major);
        }
}

// ---------------- gates ----------------
__global__ void k_gate(const float* __restrict__ hi,
                       const float* __restrict__ bxz, const float* __restrict__ bhz,
                       const float* __restrict__ bxr, const float* __restrict__ bhr, int n) {
    int idx = blockIdx.x * blockDim.x + threadIdx.x;
    if (idx >= n * 32) return;
    int m = idx >> 5, j = idx & 31;
    const float4* P4 = (const float4*)g_P;
    float4 pz = P4[(size_t)m * 96 + j];
    float4 pr = P4[(size_t)m * 96 + 32 + j];
    float4 b0 = __ldg((const float4*)bxz + j);
    float4 b1 = __ldg((const float4*)bhz + j);
    float4 b2 = __ldg((const float4*)bxr + j);
    float4 b3 = __ldg((const float4*)bhr + j);
    float4 hv = __ldg((const float4*)hi + (size_t)m * 32 + j);

    float4 z, rh;
    z.x = sigmoidf(pz.x + b0.x + b1.x); z.y = sigmoidf(pz.y + b0.y + b1.y);
    z.z = sigmoidf(pz.z + b0.z + b1.z); z.w = sigmoidf(pz.w + b0.w + b1.w);
    float rx = sigmoidf(pr.x + b2.x + b3.x), ry = sigmoidf(pr.y + b2.y + b3.y);
    float rz = sigmoidf(pr.z + b2.z + b3.z), rw = sigmoidf(pr.w + b2.w + b3.w);
    rh.x = rx * hv.x; rh.y = ry * hv.y; rh.z = rz * hv.z; rh.w = rw * hv.w;

    ((float4*)g_z)[(size_t)m * 32 + j] = z;
    ((float4*)g_rh)[(size_t)m * 32 + j] = rh;
}

// ---------------- final ----------------
__global__ void k_final(const float* __restrict__ hi,
                        const float* __restrict__ bxh, const float* __restrict__ bhh,
                        float* __restrict__ out, int n) {
    int idx = blockIdx.x * blockDim.x + threadIdx.x;
    if (idx >= n * 32) return;
    int m = idx >> 5, j = idx & 31;
    float4 pxh = ((const float4*)g_P)[(size_t)m * 96 + 64 + j];
    float4 q = ((const float4*)g_Q)[(size_t)m * 32 + j];
    float4 b0 = __ldg((const float4*)bxh + j);
    float4 b1 = __ldg((const float4*)bhh + j);
    float4 zv = ((const float4*)g_z)[(size_t)m * 32 + j];
    float4 hv = __ldg((const float4*)hi + (size_t)m * 32 + j);
    float4 ho;
    float ht;
    ht = tanhf(pxh.x + q.x + b0.x + b1.x); ho.x = zv.x * hv.x + (1.0f - zv.x) * ht;
    ht = tanhf(pxh.y + q.y + b0.y + b1.y); ho.y = zv.y * hv.y + (1.0f - zv.y) * ht;
    ht = tanhf(pxh.z + q.z + b0.z + b1.z); ho.z = zv.z * hv.z + (1.0f - zv.z) * ht;
    ht = tanhf(pxh.w + q.w + b0.w + b1.w); ho.w = zv.w * hv.w + (1.0f - zv.w) * ht;
    ((float4*)out)[(size_t)m * 32 + j] = ho;
}

// ---------------- host ----------------
extern "C" void kernel_launch(void* const* d_in, const int* in_sizes, int n_in,
                              void* d_out, int out_size) {
    const float* x   = (const float*)d_in[0];
    const int*   ei  = (const int*)d_in[1];
    const float* ew  = (const float*)d_in[2];
    const float* h   = (const float*)d_in[3];
    const float* Wxz = (const float*)d_in[4];  const float* bxz = (const float*)d_in[5];
    const float* Whz = (const float*)d_in[6];  const float* bhz = (const float*)d_in[7];
    const float* Wxr = (const float*)d_in[8];  const float* bxr = (const float*)d_in[9];
    const float* Whr = (const float*)d_in[10]; const float* bhr = (const float*)d_in[11];
    const float* Wxh = (const float*)d_in[12]; const float* bxh = (const float*)d_in[13];
    const float* Whh = (const float*)d_in[14]; const float* bhh = (const float*)d_in[15];
    float* out = (float*)d_out;

    int N = in_sizes[0] / D;
    int E = in_sizes[2];
    int L = in_sizes[5] / D;

    const int* rowi = ei;
    const int* coli = ei + E;

    float *p_sxh, *p_P, *p_Sr, *p_Q;
    __nv_bfloat16 *p_w1h, *p_w1l, *p_w2h, *p_w2l;
    cudaGetSymbolAddress((void**)&p_sxh, g_sxh);
    cudaGetSymbolAddress((void**)&p_P,   g_P);
    cudaGetSymbolAddress((void**)&p_Sr,  g_Sr);
    cudaGetSymbolAddress((void**)&p_Q,   g_Q);
    cudaGetSymbolAddress((void**)&p_w1h, g_Wt1hi);
    cudaGetSymbolAddress((void**)&p_w1l, g_Wt1lo);
    cudaGetSymbolAddress((void**)&p_w2h, g_Wt2hi);
    cudaGetSymbolAddress((void**)&p_w2l, g_Wt2lo);

    int smem1 = 2 * (128 + 64) * (256 + 16) * 2;  // K=256
    int smem2 = 2 * (128 + 64) * (128 + 16) * 2;  // K=128
    cudaFuncSetAttribute(k_wgemm, cudaFuncAttributeMaxDynamicSharedMemorySize, smem1);

    // ---- one-time: degrees, CSR build ----
    k_deg_init<<<(N + 255) / 256, 256>>>(N);
    k_deg_edges<<<(E + 255) / 256, 256>>>(coli, ew, E);
    k_dinv<<<(N + 255) / 256, 256>>>(N);
    k_scan<<<1, 1024>>>(N);
    k_place<<<(E + 255) / 256, 256>>>(rowi, coli, ew, E);

    int nwblocks = (N * 32 + 255) / 256;  // warp per node
    int mtiles = (N + 127) / 128;

    for (int i = 0; i < L; i++) {
        const float* xin = (i == 0) ? x : out + (size_t)(i - 1) * N * D;
        const float* hi = h + (size_t)i * N * D;

        k_build_wt1<<<(384 * 256 + 255) / 256, 256>>>(Wxz + (size_t)i * D * D, Whz + (size_t)i * D * D,
                                                      Wxr + (size_t)i * D * D, Whr + (size_t)i * D * D,
                                                      Wxh + (size_t)i * D * D);
        k_build_wt2<<<(128 * 128 + 255) / 256, 256>>>(Whh + (size_t)i * D * D);
        k_csr256<<<nwblocks, 256>>>(xin, hi, N);
        k_wgemm<<<dim3(mtiles, 6), 256, smem1>>>(p_sxh, p_w1h, p_w1l, p_P, N, 256, 384);
        k_gate<<<(N * 32 + 255) / 256, 256>>>(hi, bxz + i * D, bhz + i * D, bxr + i * D, bhr + i * D, N);
        k_csr128<<<nwblocks, 256>>>(N);
        k_wgemm<<<dim3(mtiles, 2), 256, smem2>>>(p_Sr, p_w2h, p_w2l, p_Q, N, 128, 128);
        k_final<<<(N * 32 + 255) / 256, 256>>>(hi, bxh + i * D, bhh + i * D, out + (size_t)i * N * D, N);
    }
}

// round 5
// speedup vs baseline: 2.0697x; 1.2120x over previous
#include <cuda_runtime.h>
#include <cuda_bf16.h>
#include <mma.h>
#include <math.h>
#include <stdint.h>

using namespace nvcuda;

#define D 128
#define MAXN 50432
#define MAXE 1700000

// ---------------- scratch (device globals: allocation-free) ----------------
__device__ float g_dinv[MAXN];                 // deg -> rsqrt(deg)
__device__ int   g_cnt[MAXN];                  // in-degree histogram
__device__ int   g_off[MAXN + 1];              // CSR offsets
__device__ int   g_cur[MAXN];                  // placement cursors
__device__ int   g_tmp[MAXN];                  // scan scratch (inclusive per-block)
__device__ int   g_part[64];                   // scan block partials
__device__ int2  g_srt[MAXE];                  // packed (row, norm) per edge, grouped by col
__device__ float g_sxh[(size_t)MAXN * 256];    // [S@xin | S@h]   (GEMM1 A)
__device__ float g_P[(size_t)MAXN * 384];      // GEMM1 out: [z_pre | r_pre | xh_part]
__device__ float g_rh[(size_t)MAXN * D];       // r * h
__device__ float g_Sr[(size_t)MAXN * D];       // S @ (r*h)      (GEMM2 A)
__device__ float g_Q[(size_t)MAXN * D];        // GEMM2 out
__device__ float g_z[(size_t)MAXN * D];        // z gate
__device__ __nv_bfloat16 g_Wt1hi[384 * 256];   // GEMM1 B (n-major, split)
__device__ __nv_bfloat16 g_Wt1lo[384 * 256];
__device__ __nv_bfloat16 g_Wt2hi[128 * 128];   // GEMM2 B (n-major, split)
__device__ __nv_bfloat16 g_Wt2lo[128 * 128];

__device__ __forceinline__ float sigmoidf(float x) { return 1.0f / (1.0f + expf(-x)); }

// ---------------- degree / histogram ----------------
__global__ void k_deg_init(int n) {
    int i = blockIdx.x * blockDim.x + threadIdx.x;
    if (i < n) { g_dinv[i] = 1.0f; g_cnt[i] = 0; }
}
__global__ void k_deg_edges(const int* __restrict__ coli, const float* __restrict__ w, int E) {
    int e = blockIdx.x * blockDim.x + threadIdx.x;
    if (e < E) {
        int c = coli[e];
        atomicAdd(&g_dinv[c], w[e]);
        atomicAdd(&g_cnt[c], 1);
    }
}
__global__ void k_dinv(int n) {
    int i = blockIdx.x * blockDim.x + threadIdx.x;
    if (i < n) {
        float d = g_dinv[i];
        g_dinv[i] = (d > 0.0f) ? rsqrtf(d) : 0.0f;
    }
}

// ---------------- multi-block scan ----------------
// Phase 1: per-block inclusive scan of g_cnt (1024 elems/block) -> g_tmp, totals -> g_part
__global__ void __launch_bounds__(1024)
k_scan1(int n) {
    __shared__ int warpsum[32];
    int i = blockIdx.x * 1024 + threadIdx.x;
    int lane = threadIdx.x & 31, wid = threadIdx.x >> 5;
    int v = (i < n) ? g_cnt[i] : 0;
    int x = v;
#pragma unroll
    for (int o = 1; o < 32; o <<= 1) {
        int t = __shfl_up_sync(~0u, x, o);
        if (lane >= o) x += t;
    }
    if (lane == 31) warpsum[wid] = x;
    __syncthreads();
    if (wid == 0) {
        int s = warpsum[lane];
#pragma unroll
        for (int o = 1; o < 32; o <<= 1) {
            int t = __shfl_up_sync(~0u, s, o);
            if (lane >= o) s += t;
        }
        warpsum[lane] = s;
    }
    __syncthreads();
    int incl = x + ((wid > 0) ? warpsum[wid - 1] : 0);
    if (i < n) g_tmp[i] = incl;
    if (threadIdx.x == 1023) g_part[blockIdx.x] = incl;
}
// Phase 2: exclusive scan of block partials (nb <= 64), single 64-thread block
__global__ void k_scan2(int nb) {
    __shared__ int sm[64];
    int t = threadIdx.x;
    sm[t] = (t < nb) ? g_part[t] : 0;
    __syncthreads();
    for (int o = 1; o < 64; o <<= 1) {
        int v = (t >= o) ? sm[t - o] : 0;
        __syncthreads();
        sm[t] += v;
        __syncthreads();
    }
    g_part[t] = (t > 0) ? sm[t - 1] : 0;
}
// Phase 3: add back -> g_off (exclusive, with off[0]=0) and g_cur
__global__ void k_scan3(int n) {
    int i = blockIdx.x * blockDim.x + threadIdx.x;
    if (i >= n) return;
    int off = g_tmp[i] + g_part[i >> 10];
    g_off[i + 1] = off;
    g_cur[i] = off - g_cnt[i];
    if (i == 0) g_off[0] = 0;
}

// ---------------- placement scatter: (row, norm) grouped by col ----------------
__global__ void k_place(const int* __restrict__ rowi, const int* __restrict__ coli,
                        const float* __restrict__ w, int E) {
    int e = blockIdx.x * blockDim.x + threadIdx.x;
    if (e >= E) return;
    int r = rowi[e], c = coli[e];
    float nrm = w[e] * __ldg(g_dinv + r) * __ldg(g_dinv + c);
    int pos = atomicAdd(&g_cur[c], 1);
    g_srt[pos] = make_int2(r, __float_as_int(nrm));
}

// ---------------- weight build (transposed + bf16 split) ----------------
__global__ void k_build_wt1(const float* __restrict__ Wxz, const float* __restrict__ Whz,
                            const float* __restrict__ Wxr, const float* __restrict__ Whr,
                            const float* __restrict__ Wxh) {
    int idx = blockIdx.x * blockDim.x + threadIdx.x;  // 384*256, n-major
    if (idx >= 384 * 256) return;
    int n = idx / 256, k = idx % 256;
    int blk = n >> 7, nn = n & 127;
    float v;
    if (blk == 0)      v = (k < 128) ? Wxz[k * 128 + nn] : Whz[(k - 128) * 128 + nn];
    else if (blk == 1) v = (k < 128) ? Wxr[k * 128 + nn] : Whr[(k - 128) * 128 + nn];
    else               v = (k < 128) ? Wxh[k * 128 + nn] : 0.0f;
    __nv_bfloat16 hi = __float2bfloat16(v);
    g_Wt1hi[idx] = hi;
    g_Wt1lo[idx] = __float2bfloat16(v - __bfloat162float(hi));
}
__global__ void k_build_wt2(const float* __restrict__ Whh) {
    int idx = blockIdx.x * blockDim.x + threadIdx.x;  // 128*128, n-major
    if (idx >= 128 * 128) return;
    int n = idx / 128, k = idx % 128;
    float v = Whh[k * 128 + n];
    __nv_bfloat16 hi = __float2bfloat16(v);
    g_Wt2hi[idx] = hi;
    g_Wt2lo[idx] = __float2bfloat16(v - __bfloat162float(hi));
}

// ---------------- CSR gather: 256-wide ([x|h] -> g_sxh), warp per node ----------------
__global__ void __launch_bounds__(256)
k_csr256(const float* __restrict__ xin, const float* __restrict__ hi, int n) {
    int node = (blockIdx.x * blockDim.x + threadIdx.x) >> 5;
    if (node >= n) return;
    int lane = threadIdx.x & 31;
    const float4* x4 = (const float4*)xin;
    const float4* h4 = (const float4*)hi;
    float di = __ldg(g_dinv + node);
    float s = di * di;
    float4 ax = __ldg(x4 + (size_t)node * 32 + lane);
    float4 ah = __ldg(h4 + (size_t)node * 32 + lane);
    ax.x *= s; ax.y *= s; ax.z *= s; ax.w *= s;
    ah.x *= s; ah.y *= s; ah.z *= s; ah.w *= s;
    int e0 = __ldg(g_off + node), e1 = __ldg(g_off + node + 1);
#pragma unroll 4
    for (int e = e0; e < e1; e++) {
        int2 p = __ldg(g_srt + e);
        float nrm = __int_as_float(p.y);
        float4 vx = __ldg(x4 + (size_t)p.x * 32 + lane);
        float4 vh = __ldg(h4 + (size_t)p.x * 32 + lane);
        ax.x += nrm * vx.x; ax.y += nrm * vx.y; ax.z += nrm * vx.z; ax.w += nrm * vx.w;
        ah.x += nrm * vh.x; ah.y += nrm * vh.y; ah.z += nrm * vh.z; ah.w += nrm * vh.w;
    }
    float4* dst = (float4*)g_sxh + (size_t)node * 64;
    dst[lane] = ax;
    dst[32 + lane] = ah;
}

// ---------------- CSR gather: 128-wide (g_rh -> g_Sr), warp per node ----------------
__global__ void __launch_bounds__(256)
k_csr128(int n) {
    int node = (blockIdx.x * blockDim.x + threadIdx.x) >> 5;
    if (node >= n) return;
    int lane = threadIdx.x & 31;
    const float4* r4 = (const float4*)g_rh;
    float di = __ldg(g_dinv + node);
    float s = di * di;
    float4 acc = r4[(size_t)node * 32 + lane];
    acc.x *= s; acc.y *= s; acc.z *= s; acc.w *= s;
    int e0 = __ldg(g_off + node), e1 = __ldg(g_off + node + 1);
#pragma unroll 4
    for (int e = e0; e < e1; e++) {
        int2 p = __ldg(g_srt + e);
        float nrm = __int_as_float(p.y);
        float4 v = __ldg(r4 + (size_t)p.x * 32 + lane);
        acc.x += nrm * v.x; acc.y += nrm * v.y; acc.z += nrm * v.z; acc.w += nrm * v.w;
    }
    ((float4*)g_Sr)[(size_t)node * 32 + lane] = acc;
}

// ---------------- WMMA split-bf16 GEMM (A loaded once, loop over N tiles) --------
// C[128 x 64*ntiles] = A[fp32, M x K] @ B^T, B n-major [64*ntiles x K] bf16 hi/lo.
// 3-pass: Ahi*Bhi + Ahi*Blo + Alo*Bhi, fp32 accumulate. Grid: (ceil(M/128)).
__global__ void __launch_bounds__(256, 1)
k_wgemm(const float* __restrict__ A, const __nv_bfloat16* __restrict__ Bhi,
        const __nv_bfloat16* __restrict__ Blo, float* __restrict__ C,
        int M, int K, int ldC, int ntiles) {
    extern __shared__ char smem[];
    const int tid = threadIdx.x;
    const int blockRow = blockIdx.x * 128;
    const int ldS = K + 16;

    __nv_bfloat16* Ahi = (__nv_bfloat16*)smem;
    __nv_bfloat16* Alo = Ahi + 128 * ldS;
    __nv_bfloat16* Bh  = Alo + 128 * ldS;
    __nv_bfloat16* Bl  = Bh + 64 * ldS;

    // ---- load A fp32 -> split bf16 hi/lo into SMEM (once) ----
    {
        const int K4 = K >> 2;
        for (int idx = tid; idx < 128 * K4; idx += 256) {
            int r = idx / K4, c = (idx % K4) * 4;
            float4 v = __ldg((const float4*)(A + (size_t)(blockRow + r) * K + c));
            __nv_bfloat16 h0 = __float2bfloat16(v.x), h1 = __float2bfloat16(v.y);
            __nv_bfloat16 h2 = __float2bfloat16(v.z), h3 = __float2bfloat16(v.w);
            __nv_bfloat16 l0 = __float2bfloat16(v.x - __bfloat162float(h0));
            __nv_bfloat16 l1 = __float2bfloat16(v.y - __bfloat162float(h1));
            __nv_bfloat16 l2 = __float2bfloat16(v.z - __bfloat162float(h2));
            __nv_bfloat16 l3 = __float2bfloat16(v.w - __bfloat162float(h3));
            uint32_t hw0 = ((uint32_t)__bfloat16_as_ushort(h1) << 16) | __bfloat16_as_ushort(h0);
            uint32_t hw1 = ((uint32_t)__bfloat16_as_ushort(h3) << 16) | __bfloat16_as_ushort(h2);
            uint32_t lw0 = ((uint32_t)__bfloat16_as_ushort(l1) << 16) | __bfloat16_as_ushort(l0);
            uint32_t lw1 = ((uint32_t)__bfloat16_as_ushort(l3) << 16) | __bfloat16_as_ushort(l2);
            *(uint2*)(Ahi + (size_t)r * ldS + c) = make_uint2(hw0, hw1);
            *(uint2*)(Alo + (size_t)r * ldS + c) = make_uint2(lw0, lw1);
        }
    }

    const int warpId = tid >> 5;
    const int wm = warpId & 3;
    const int wn = warpId >> 2;
    const int row0 = wm * 32;
    const int col0 = wn * 32;
    const int K8 = K >> 3;

    for (int nt = 0; nt < ntiles; nt++) {
        const int n0 = nt * 64;
        __syncthreads();  // previous iter done reading Bh/Bl (and A ready on first iter)
        for (int idx = tid; idx < 64 * K8; idx += 256) {
            int n = idx / K8, c = (idx % K8) * 8;
            uint4 vh = __ldg((const uint4*)(Bhi + (size_t)(n0 + n) * K + c));
            uint4 vl = __ldg((const uint4*)(Blo + (size_t)(n0 + n) * K + c));
            *(uint4*)(Bh + (size_t)n * ldS + c) = vh;
            *(uint4*)(Bl + (size_t)n * ldS + c) = vl;
        }
        __syncthreads();

        wmma::fragment<wmma::accumulator, 16, 16, 16, float> acc[2][2];
#pragma unroll
        for (int i = 0; i < 2; i++)
#pragma unroll
            for (int j = 0; j < 2; j++) wmma::fill_fragment(acc[i][j], 0.0f);

        for (int k0 = 0; k0 < K; k0 += 16) {
            wmma::fragment<wmma::matrix_a, 16, 16, 16, __nv_bfloat16, wmma::row_major> ah[2], al[2];
            wmma::fragment<wmma::matrix_b, 16, 16, 16, __nv_bfloat16, wmma::col_major> bh[2], bl[2];
#pragma unroll
            for (int i = 0; i < 2; i++) {
                wmma::load_matrix_sync(ah[i], Ahi + (size_t)(row0 + i * 16) * ldS + k0, ldS);
                wmma::load_matrix_sync(al[i], Alo + (size_t)(row0 + i * 16) * ldS + k0, ldS);
            }
#pragma unroll
            for (int j = 0; j < 2; j++) {
                wmma::load_matrix_sync(bh[j], Bh + (size_t)(col0 + j * 16) * ldS + k0, ldS);
                wmma::load_matrix_sync(bl[j], Bl + (size_t)(col0 + j * 16) * ldS + k0, ldS);
            }
#pragma unroll
            for (int i = 0; i < 2; i++)
#pragma unroll
                for (int j = 0; j < 2; j++) {
                    wmma::mma_sync(acc[i][j], ah[i], bh[j], acc[i][j]);
                    wmma::mma_sync(acc[i][j], ah[i], bl[j], acc[i][j]);
                    wmma::mma_sync(acc[i][j], al[i], bh[j], acc[i][j]);
                }
        }

#pragma unroll
        for (int i = 0; i < 2; i++)
#pragma unroll
            for (int j = 0; j < 2; j++) {
                float* cp = C + (size_t)(blockRow + row0 + i * 16) * ldC + n0 + col0 + j * 16;
                wmma::store_matrix_sync(cp, acc[i][j], ldC, wmma::mem_row_major);
            }
    }
}

// ---------------- gates ----------------
__global__ void k_gate(const float* __restrict__ hi,
                       const float* __restrict__ bxz, const float* __restrict__ bhz,
                       const float* __restrict__ bxr, const float* __restrict__ bhr, int n) {
    int idx = blockIdx.x * blockDim.x + threadIdx.x;
    if (idx >= n * 32) return;
    int m = idx >> 5, j = idx & 31;
    const float4* P4 = (const float4*)g_P;
    float4 pz = P4[(size_t)m * 96 + j];
    float4 pr = P4[(size_t)m * 96 + 32 + j];
    float4 b0 = __ldg((const float4*)bxz + j);
    float4 b1 = __ldg((const float4*)bhz + j);
    float4 b2 = __ldg((const float4*)bxr + j);
    float4 b3 = __ldg((const float4*)bhr + j);
    float4 hv = __ldg((const float4*)hi + (size_t)m * 32 + j);

    float4 z, rh;
    z.x = sigmoidf(pz.x + b0.x + b1.x); z.y = sigmoidf(pz.y + b0.y + b1.y);
    z.z = sigmoidf(pz.z + b0.z + b1.z); z.w = sigmoidf(pz.w + b0.w + b1.w);
    float rx = sigmoidf(pr.x + b2.x + b3.x), ry = sigmoidf(pr.y + b2.y + b3.y);
    float rz = sigmoidf(pr.z + b2.z + b3.z), rw = sigmoidf(pr.w + b2.w + b3.w);
    rh.x = rx * hv.x; rh.y = ry * hv.y; rh.z = rz * hv.z; rh.w = rw * hv.w;

    ((float4*)g_z)[(size_t)m * 32 + j] = z;
    ((float4*)g_rh)[(size_t)m * 32 + j] = rh;
}

// ---------------- final ----------------
__global__ void k_final(const float* __restrict__ hi,
                        const float* __restrict__ bxh, const float* __restrict__ bhh,
                        float* __restrict__ out, int n) {
    int idx = blockIdx.x * blockDim.x + threadIdx.x;
    if (idx >= n * 32) return;
    int m = idx >> 5, j = idx & 31;
    float4 pxh = ((const float4*)g_P)[(size_t)m * 96 + 64 + j];
    float4 q = ((const float4*)g_Q)[(size_t)m * 32 + j];
    float4 b0 = __ldg((const float4*)bxh + j);
    float4 b1 = __ldg((const float4*)bhh + j);
    float4 zv = ((const float4*)g_z)[(size_t)m * 32 + j];
    float4 hv = __ldg((const float4*)hi + (size_t)m * 32 + j);
    float4 ho;
    float ht;
    ht = tanhf(pxh.x + q.x + b0.x + b1.x); ho.x = zv.x * hv.x + (1.0f - zv.x) * ht;
    ht = tanhf(pxh.y + q.y + b0.y + b1.y); ho.y = zv.y * hv.y + (1.0f - zv.y) * ht;
    ht = tanhf(pxh.z + q.z + b0.z + b1.z); ho.z = zv.z * hv.z + (1.0f - zv.z) * ht;
    ht = tanhf(pxh.w + q.w + b0.w + b1.w); ho.w = zv.w * hv.w + (1.0f - zv.w) * ht;
    ((float4*)out)[(size_t)m * 32 + j] = ho;
}

// ---------------- host ----------------
extern "C" void kernel_launch(void* const* d_in, const int* in_sizes, int n_in,
                              void* d_out, int out_size) {
    const float* x   = (const float*)d_in[0];
    const int*   ei  = (const int*)d_in[1];
    const float* ew  = (const float*)d_in[2];
    const float* h   = (const float*)d_in[3];
    const float* Wxz = (const float*)d_in[4];  const float* bxz = (const float*)d_in[5];
    const float* Whz = (const float*)d_in[6];  const float* bhz = (const float*)d_in[7];
    const float* Wxr = (const float*)d_in[8];  const float* bxr = (const float*)d_in[9];
    const float* Whr = (const float*)d_in[10]; const float* bhr = (const float*)d_in[11];
    const float* Wxh = (const float*)d_in[12]; const float* bxh = (const float*)d_in[13];
    const float* Whh = (const float*)d_in[14]; const float* bhh = (const float*)d_in[15];
    float* out = (float*)d_out;

    int N = in_sizes[0] / D;
    int E = in_sizes[2];
    int L = in_sizes[5] / D;

    const int* rowi = ei;
    const int* coli = ei + E;

    float *p_sxh, *p_P, *p_Sr, *p_Q;
    __nv_bfloat16 *p_w1h, *p_w1l, *p_w2h, *p_w2l;
    cudaGetSymbolAddress((void**)&p_sxh, g_sxh);
    cudaGetSymbolAddress((void**)&p_P,   g_P);
    cudaGetSymbolAddress((void**)&p_Sr,  g_Sr);
    cudaGetSymbolAddress((void**)&p_Q,   g_Q);
    cudaGetSymbolAddress((void**)&p_w1h, g_Wt1hi);
    cudaGetSymbolAddress((void**)&p_w1l, g_Wt1lo);
    cudaGetSymbolAddress((void**)&p_w2h, g_Wt2hi);
    cudaGetSymbolAddress((void**)&p_w2l, g_Wt2lo);

    int smem1 = 2 * (128 + 64) * (256 + 16) * 2;  // K=256
    int smem2 = 2 * (128 + 64) * (128 + 16) * 2;  // K=128
    cudaFuncSetAttribute(k_wgemm, cudaFuncAttributeMaxDynamicSharedMemorySize, smem1);

    // ---- one-time: degrees, CSR build ----
    k_deg_init<<<(N + 255) / 256, 256>>>(N);
    k_deg_edges<<<(E + 255) / 256, 256>>>(coli, ew, E);
    k_dinv<<<(N + 255) / 256, 256>>>(N);
    int nscan = (N + 1023) / 1024;
    k_scan1<<<nscan, 1024>>>(N);
    k_scan2<<<1, 64>>>(nscan);
    k_scan3<<<(N + 255) / 256, 256>>>(N);
    k_place<<<(E + 255) / 256, 256>>>(rowi, coli, ew, E);

    int nwblocks = (N * 32 + 255) / 256;  // warp per node
    int mtiles = (N + 127) / 128;

    for (int i = 0; i < L; i++) {
        const float* xin = (i == 0) ? x : out + (size_t)(i - 1) * N * D;
        const float* hi = h + (size_t)i * N * D;

        k_build_wt1<<<(384 * 256 + 255) / 256, 256>>>(Wxz + (size_t)i * D * D, Whz + (size_t)i * D * D,
                                                      Wxr + (size_t)i * D * D, Whr + (size_t)i * D * D,
                                                      Wxh + (size_t)i * D * D);
        k_build_wt2<<<(128 * 128 + 255) / 256, 256>>>(Whh + (size_t)i * D * D);
        k_csr256<<<nwblocks, 256>>>(xin, hi, N);
        k_wgemm<<<mtiles, 256, smem1>>>(p_sxh, p_w1h, p_w1l, p_P, N, 256, 384, 6);
        k_gate<<<(N * 32 + 255) / 256, 256>>>(hi, bxz + i * D, bhz + i * D, bxr + i * D, bhr + i * D, N);
        k_csr128<<<nwblocks, 256>>>(N);
        k_wgemm<<<mtiles, 256, smem2>>>(p_Sr, p_w2h, p_w2l, p_Q, N, 128, 128, 2);
        k_final<<<(N * 32 + 255) / 256, 256>>>(hi, bxh + i * D, bhh + i * D, out + (size_t)i * N * D, N);
    }
}

// round 6
// speedup vs baseline: 2.2970x; 1.1099x over previous
#include <cuda_runtime.h>
#include <cuda_bf16.h>
#include <cuda_fp16.h>
#include <mma.h>
#include <math.h>
#include <stdint.h>

using namespace nvcuda;

#define D 128
#define MAXN 50432
#define MAXE 1700000

// ---------------- scratch (device globals: allocation-free) ----------------
__device__ float g_dinv[MAXN];                 // deg -> rsqrt(deg)
__device__ int   g_cnt[MAXN];                  // in-degree histogram
__device__ int   g_off[MAXN + 1];              // CSR offsets
__device__ int   g_cur[MAXN];                  // placement cursors
__device__ int   g_tmp[MAXN];                  // scan scratch
__device__ int   g_part[64];                   // scan block partials
__device__ int2  g_srt[MAXE];                  // packed (row, norm) per edge, grouped by col
__device__ __half g_xhh[(size_t)MAXN * 256];   // [x|h] fp16 gather source
__device__ __half g_rhh[(size_t)MAXN * D];     // r*h fp16 gather source
__device__ float g_sxh[(size_t)MAXN * 256];    // [S@xin | S@h]   (GEMM1 A, fp32)
__device__ float g_P[(size_t)MAXN * 384];      // GEMM1 out: [z_pre | r_pre | xh_part]
__device__ float g_Sr[(size_t)MAXN * D];       // S @ (r*h)      (GEMM2 A, fp32)
__device__ float g_Q[(size_t)MAXN * D];        // GEMM2 out
__device__ float g_z[(size_t)MAXN * D];        // z gate
__device__ __nv_bfloat16 g_Wt1hi[384 * 256];   // GEMM1 B (n-major, split)
__device__ __nv_bfloat16 g_Wt1lo[384 * 256];
__device__ __nv_bfloat16 g_Wt2hi[128 * 128];   // GEMM2 B (n-major, split)
__device__ __nv_bfloat16 g_Wt2lo[128 * 128];

__device__ __forceinline__ float sigmoidf(float x) { return 1.0f / (1.0f + expf(-x)); }

// ---------------- degree / histogram ----------------
__global__ void k_deg_init(int n) {
    int i = blockIdx.x * blockDim.x + threadIdx.x;
    if (i < n) { g_dinv[i] = 1.0f; g_cnt[i] = 0; }
}
__global__ void k_deg_edges(const int* __restrict__ coli, const float* __restrict__ w, int E) {
    int e = blockIdx.x * blockDim.x + threadIdx.x;
    if (e < E) {
        int c = coli[e];
        atomicAdd(&g_dinv[c], w[e]);
        atomicAdd(&g_cnt[c], 1);
    }
}
__global__ void k_dinv(int n) {
    int i = blockIdx.x * blockDim.x + threadIdx.x;
    if (i < n) {
        float d = g_dinv[i];
        g_dinv[i] = (d > 0.0f) ? rsqrtf(d) : 0.0f;
    }
}

// ---------------- multi-block scan ----------------
__global__ void __launch_bounds__(1024)
k_scan1(int n) {
    __shared__ int warpsum[32];
    int i = blockIdx.x * 1024 + threadIdx.x;
    int lane = threadIdx.x & 31, wid = threadIdx.x >> 5;
    int v = (i < n) ? g_cnt[i] : 0;
    int x = v;
#pragma unroll
    for (int o = 1; o < 32; o <<= 1) {
        int t = __shfl_up_sync(~0u, x, o);
        if (lane >= o) x += t;
    }
    if (lane == 31) warpsum[wid] = x;
    __syncthreads();
    if (wid == 0) {
        int s = warpsum[lane];
#pragma unroll
        for (int o = 1; o < 32; o <<= 1) {
            int t = __shfl_up_sync(~0u, s, o);
            if (lane >= o) s += t;
        }
        warpsum[lane] = s;
    }
    __syncthreads();
    int incl = x + ((wid > 0) ? warpsum[wid - 1] : 0);
    if (i < n) g_tmp[i] = incl;
    if (threadIdx.x == 1023) g_part[blockIdx.x] = incl;
}
__global__ void k_scan2(int nb) {
    __shared__ int sm[64];
    int t = threadIdx.x;
    sm[t] = (t < nb) ? g_part[t] : 0;
    __syncthreads();
    for (int o = 1; o < 64; o <<= 1) {
        int v = (t >= o) ? sm[t - o] : 0;
        __syncthreads();
        sm[t] += v;
        __syncthreads();
    }
    g_part[t] = (t > 0) ? sm[t - 1] : 0;
}
__global__ void k_scan3(int n) {
    int i = blockIdx.x * blockDim.x + threadIdx.x;
    if (i >= n) return;
    int off = g_tmp[i] + g_part[i >> 10];
    g_off[i + 1] = off;
    g_cur[i] = off - g_cnt[i];
    if (i == 0) g_off[0] = 0;
}

// ---------------- placement scatter ----------------
__global__ void k_place(const int* __restrict__ rowi, const int* __restrict__ coli,
                        const float* __restrict__ w, int E) {
    int e = blockIdx.x * blockDim.x + threadIdx.x;
    if (e >= E) return;
    int r = rowi[e], c = coli[e];
    float nrm = w[e] * __ldg(g_dinv + r) * __ldg(g_dinv + c);
    int pos = atomicAdd(&g_cur[c], 1);
    g_srt[pos] = make_int2(r, __float_as_int(nrm));
}

// ---------------- weight build (transposed + bf16 split) ----------------
__global__ void k_build_wt1(const float* __restrict__ Wxz, const float* __restrict__ Whz,
                            const float* __restrict__ Wxr, const float* __restrict__ Whr,
                            const float* __restrict__ Wxh) {
    int idx = blockIdx.x * blockDim.x + threadIdx.x;
    if (idx >= 384 * 256) return;
    int n = idx / 256, k = idx % 256;
    int blk = n >> 7, nn = n & 127;
    float v;
    if (blk == 0)      v = (k < 128) ? Wxz[k * 128 + nn] : Whz[(k - 128) * 128 + nn];
    else if (blk == 1) v = (k < 128) ? Wxr[k * 128 + nn] : Whr[(k - 128) * 128 + nn];
    else               v = (k < 128) ? Wxh[k * 128 + nn] : 0.0f;
    __nv_bfloat16 hi = __float2bfloat16(v);
    g_Wt1hi[idx] = hi;
    g_Wt1lo[idx] = __float2bfloat16(v - __bfloat162float(hi));
}
__global__ void k_build_wt2(const float* __restrict__ Whh) {
    int idx = blockIdx.x * blockDim.x + threadIdx.x;
    if (idx >= 128 * 128) return;
    int n = idx / 128, k = idx % 128;
    float v = Whh[k * 128 + n];
    __nv_bfloat16 hi = __float2bfloat16(v);
    g_Wt2hi[idx] = hi;
    g_Wt2lo[idx] = __float2bfloat16(v - __bfloat162float(hi));
}

// ---------------- prep: pack [x|h] fp32 -> fp16 gather rows ----------------
__global__ void k_prep(const float* __restrict__ x, const float* __restrict__ h, int n) {
    int idx = blockIdx.x * blockDim.x + threadIdx.x;  // n*32, 8 elems each
    if (idx >= n * 32) return;
    int m = idx >> 5, j = idx & 31;
    const float4* src = (j < 16) ? (const float4*)x + (size_t)m * 32 + 2 * j
                                 : (const float4*)h + (size_t)m * 32 + 2 * (j - 16);
    float4 a = __ldg(src), b = __ldg(src + 1);
    __half2 h0 = __floats2half2_rn(a.x, a.y), h1 = __floats2half2_rn(a.z, a.w);
    __half2 h2 = __floats2half2_rn(b.x, b.y), h3 = __floats2half2_rn(b.z, b.w);
    uint4 o;
    o.x = *(uint32_t*)&h0; o.y = *(uint32_t*)&h1; o.z = *(uint32_t*)&h2; o.w = *(uint32_t*)&h3;
    ((uint4*)g_xhh)[(size_t)m * 32 + j] = o;
}

// ---------------- CSR gather: 256-wide fp16 -> g_sxh fp32, warp per node ----------------
__global__ void __launch_bounds__(256)
k_csr256(int n) {
    int node = (blockIdx.x * blockDim.x + threadIdx.x) >> 5;
    if (node >= n) return;
    int lane = threadIdx.x & 31;
    const uint4* src = (const uint4*)g_xhh;
    float di = __ldg(g_dinv + node);
    float s = di * di;
    float acc[8];
    {
        uint4 v = __ldg(src + (size_t)node * 32 + lane);
        float2 f0 = __half22float2(*(__half2*)&v.x), f1 = __half22float2(*(__half2*)&v.y);
        float2 f2 = __half22float2(*(__half2*)&v.z), f3 = __half22float2(*(__half2*)&v.w);
        acc[0] = s * f0.x; acc[1] = s * f0.y; acc[2] = s * f1.x; acc[3] = s * f1.y;
        acc[4] = s * f2.x; acc[5] = s * f2.y; acc[6] = s * f3.x; acc[7] = s * f3.y;
    }
    int e0 = __ldg(g_off + node), e1 = __ldg(g_off + node + 1);
#pragma unroll 4
    for (int e = e0; e < e1; e++) {
        int2 p = __ldg(g_srt + e);
        float nrm = __int_as_float(p.y);
        uint4 v = __ldg(src + (size_t)p.x * 32 + lane);
        float2 f0 = __half22float2(*(__half2*)&v.x), f1 = __half22float2(*(__half2*)&v.y);
        float2 f2 = __half22float2(*(__half2*)&v.z), f3 = __half22float2(*(__half2*)&v.w);
        acc[0] += nrm * f0.x; acc[1] += nrm * f0.y; acc[2] += nrm * f1.x; acc[3] += nrm * f1.y;
        acc[4] += nrm * f2.x; acc[5] += nrm * f2.y; acc[6] += nrm * f3.x; acc[7] += nrm * f3.y;
    }
    float4* dst = (float4*)g_sxh + (size_t)node * 64 + 2 * lane;
    dst[0] = make_float4(acc[0], acc[1], acc[2], acc[3]);
    dst[1] = make_float4(acc[4], acc[5], acc[6], acc[7]);
}

// ---------------- CSR gather: 128-wide fp16 (g_rhh -> g_Sr), warp per node ----------------
__global__ void __launch_bounds__(256)
k_csr128(int n) {
    int node = (blockIdx.x * blockDim.x + threadIdx.x) >> 5;
    if (node >= n) return;
    int lane = threadIdx.x & 31;
    const uint2* src = (const uint2*)g_rhh;
    float di = __ldg(g_dinv + node);
    float s = di * di;
    float acc[4];
    {
        uint2 v = __ldg(src + (size_t)node * 32 + lane);
        float2 f0 = __half22float2(*(__half2*)&v.x), f1 = __half22float2(*(__half2*)&v.y);
        acc[0] = s * f0.x; acc[1] = s * f0.y; acc[2] = s * f1.x; acc[3] = s * f1.y;
    }
    int e0 = __ldg(g_off + node), e1 = __ldg(g_off + node + 1);
#pragma unroll 4
    for (int e = e0; e < e1; e++) {
        int2 p = __ldg(g_srt + e);
        float nrm = __int_as_float(p.y);
        uint2 v = __ldg(src + (size_t)p.x * 32 + lane);
        float2 f0 = __half22float2(*(__half2*)&v.x), f1 = __half22float2(*(__half2*)&v.y);
        acc[0] += nrm * f0.x; acc[1] += nrm * f0.y; acc[2] += nrm * f1.x; acc[3] += nrm * f1.y;
    }
    ((float4*)g_Sr)[(size_t)node * 32 + lane] = make_float4(acc[0], acc[1], acc[2], acc[3]);
}

// ---------------- WMMA split-bf16 GEMM (A loaded once, loop over N tiles) --------
__global__ void __launch_bounds__(256, 1)
k_wgemm(const float* __restrict__ A, const __nv_bfloat16* __restrict__ Bhi,
        const __nv_bfloat16* __restrict__ Blo, float* __restrict__ C,
        int M, int K, int ldC, int ntiles) {
    extern __shared__ char smem[];
    const int tid = threadIdx.x;
    const int blockRow = blockIdx.x * 128;
    const int ldS = K + 16;

    __nv_bfloat16* Ahi = (__nv_bfloat16*)smem;
    __nv_bfloat16* Alo = Ahi + 128 * ldS;
    __nv_bfloat16* Bh  = Alo + 128 * ldS;
    __nv_bfloat16* Bl  = Bh + 64 * ldS;

    {
        const int K4 = K >> 2;
        for (int idx = tid; idx < 128 * K4; idx += 256) {
            int r = idx / K4, c = (idx % K4) * 4;
            float4 v = __ldg((const float4*)(A + (size_t)(blockRow + r) * K + c));
            __nv_bfloat16 h0 = __float2bfloat16(v.x), h1 = __float2bfloat16(v.y);
            __nv_bfloat16 h2 = __float2bfloat16(v.z), h3 = __float2bfloat16(v.w);
            __nv_bfloat16 l0 = __float2bfloat16(v.x - __bfloat162float(h0));
            __nv_bfloat16 l1 = __float2bfloat16(v.y - __bfloat162float(h1));
            __nv_bfloat16 l2 = __float2bfloat16(v.z - __bfloat162float(h2));
            __nv_bfloat16 l3 = __float2bfloat16(v.w - __bfloat162float(h3));
            uint32_t hw0 = ((uint32_t)__bfloat16_as_ushort(h1) << 16) | __bfloat16_as_ushort(h0);
            uint32_t hw1 = ((uint32_t)__bfloat16_as_ushort(h3) << 16) | __bfloat16_as_ushort(h2);
            uint32_t lw0 = ((uint32_t)__bfloat16_as_ushort(l1) << 16) | __bfloat16_as_ushort(l0);
            uint32_t lw1 = ((uint32_t)__bfloat16_as_ushort(l3) << 16) | __bfloat16_as_ushort(l2);
            *(uint2*)(Ahi + (size_t)r * ldS + c) = make_uint2(hw0, hw1);
            *(uint2*)(Alo + (size_t)r * ldS + c) = make_uint2(lw0, lw1);
        }
    }

    const int warpId = tid >> 5;
    const int wm = warpId & 3;
    const int wn = warpId >> 2;
    const int row0 = wm * 32;
    const int col0 = wn * 32;
    const int K8 = K >> 3;

    for (int nt = 0; nt < ntiles; nt++) {
        const int n0 = nt * 64;
        __syncthreads();
        for (int idx = tid; idx < 64 * K8; idx += 256) {
            int n = idx / K8, c = (idx % K8) * 8;
            uint4 vh = __ldg((const uint4*)(Bhi + (size_t)(n0 + n) * K + c));
            uint4 vl = __ldg((const uint4*)(Blo + (size_t)(n0 + n) * K + c));
            *(uint4*)(Bh + (size_t)n * ldS + c) = vh;
            *(uint4*)(Bl + (size_t)n * ldS + c) = vl;
        }
        __syncthreads();

        wmma::fragment<wmma::accumulator, 16, 16, 16, float> acc[2][2];
#pragma unroll
        for (int i = 0; i < 2; i++)
#pragma unroll
            for (int j = 0; j < 2; j++) wmma::fill_fragment(acc[i][j], 0.0f);

        for (int k0 = 0; k0 < K; k0 += 16) {
            wmma::fragment<wmma::matrix_a, 16, 16, 16, __nv_bfloat16, wmma::row_major> ah[2], al[2];
            wmma::fragment<wmma::matrix_b, 16, 16, 16, __nv_bfloat16, wmma::col_major> bh[2], bl[2];
#pragma unroll
            for (int i = 0; i < 2; i++) {
                wmma::load_matrix_sync(ah[i], Ahi + (size_t)(row0 + i * 16) * ldS + k0, ldS);
                wmma::load_matrix_sync(al[i], Alo + (size_t)(row0 + i * 16) * ldS + k0, ldS);
            }
#pragma unroll
            for (int j = 0; j < 2; j++) {
                wmma::load_matrix_sync(bh[j], Bh + (size_t)(col0 + j * 16) * ldS + k0, ldS);
                wmma::load_matrix_sync(bl[j], Bl + (size_t)(col0 + j * 16) * ldS + k0, ldS);
            }
#pragma unroll
            for (int i = 0; i < 2; i++)
#pragma unroll
                for (int j = 0; j < 2; j++) {
                    wmma::mma_sync(acc[i][j], ah[i], bh[j], acc[i][j]);
                    wmma::mma_sync(acc[i][j], ah[i], bl[j], acc[i][j]);
                    wmma::mma_sync(acc[i][j], al[i], bh[j], acc[i][j]);
                }
        }

#pragma unroll
        for (int i = 0; i < 2; i++)
#pragma unroll
            for (int j = 0; j < 2; j++) {
                float* cp = C + (size_t)(blockRow + row0 + i * 16) * ldC + n0 + col0 + j * 16;
                wmma::store_matrix_sync(cp, acc[i][j], ldC, wmma::mem_row_major);
            }
    }
}

// ---------------- gates: z fp32, rh -> fp16 gather source ----------------
__global__ void k_gate(const float* __restrict__ hi,
                       const float* __restrict__ bxz, const float* __restrict__ bhz,
                       const float* __restrict__ bxr, const float* __restrict__ bhr, int n) {
    int idx = blockIdx.x * blockDim.x + threadIdx.x;
    if (idx >= n * 32) return;
    int m = idx >> 5, j = idx & 31;
    const float4* P4 = (const float4*)g_P;
    float4 pz = P4[(size_t)m * 96 + j];
    float4 pr = P4[(size_t)m * 96 + 32 + j];
    float4 b0 = __ldg((const float4*)bxz + j);
    float4 b1 = __ldg((const float4*)bhz + j);
    float4 b2 = __ldg((const float4*)bxr + j);
    float4 b3 = __ldg((const float4*)bhr + j);
    float4 hv = __ldg((const float4*)hi + (size_t)m * 32 + j);

    float4 z, rh;
    z.x = sigmoidf(pz.x + b0.x + b1.x); z.y = sigmoidf(pz.y + b0.y + b1.y);
    z.z = sigmoidf(pz.z + b0.z + b1.z); z.w = sigmoidf(pz.w + b0.w + b1.w);
    float rx = sigmoidf(pr.x + b2.x + b3.x), ry = sigmoidf(pr.y + b2.y + b3.y);
    float rz = sigmoidf(pr.z + b2.z + b3.z), rw = sigmoidf(pr.w + b2.w + b3.w);
    rh.x = rx * hv.x; rh.y = ry * hv.y; rh.z = rz * hv.z; rh.w = rw * hv.w;

    ((float4*)g_z)[(size_t)m * 32 + j] = z;
    __half2 p0 = __floats2half2_rn(rh.x, rh.y), p1 = __floats2half2_rn(rh.z, rh.w);
    uint2 packed;
    packed.x = *(uint32_t*)&p0; packed.y = *(uint32_t*)&p1;
    ((uint2*)g_rhh)[(size_t)m * 32 + j] = packed;
}

// ---------------- final ----------------
__global__ void k_final(const float* __restrict__ hi,
                        const float* __restrict__ bxh, const float* __restrict__ bhh,
                        float* __restrict__ out, int n) {
    int idx = blockIdx.x * blockDim.x + threadIdx.x;
    if (idx >= n * 32) return;
    int m = idx >> 5, j = idx & 31;
    float4 pxh = ((const float4*)g_P)[(size_t)m * 96 + 64 + j];
    float4 q = ((const float4*)g_Q)[(size_t)m * 32 + j];
    float4 b0 = __ldg((const float4*)bxh + j);
    float4 b1 = __ldg((const float4*)bhh + j);
    float4 zv = ((const float4*)g_z)[(size_t)m * 32 + j];
    float4 hv = __ldg((const float4*)hi + (size_t)m * 32 + j);
    float4 ho;
    float ht;
    ht = tanhf(pxh.x + q.x + b0.x + b1.x); ho.x = zv.x * hv.x + (1.0f - zv.x) * ht;
    ht = tanhf(pxh.y + q.y + b0.y + b1.y); ho.y = zv.y * hv.y + (1.0f - zv.y) * ht;
    ht = tanhf(pxh.z + q.z + b0.z + b1.z); ho.z = zv.z * hv.z + (1.0f - zv.z) * ht;
    ht = tanhf(pxh.w + q.w + b0.w + b1.w); ho.w = zv.w * hv.w + (1.0f - zv.w) * ht;
    ((float4*)out)[(size_t)m * 32 + j] = ho;
}

// ---------------- host ----------------
extern "C" void kernel_launch(void* const* d_in, const int* in_sizes, int n_in,
                              void* d_out, int out_size) {
    const float* x   = (const float*)d_in[0];
    const int*   ei  = (const int*)d_in[1];
    const float* ew  = (const float*)d_in[2];
    const float* h   = (const float*)d_in[3];
    const float* Wxz = (const float*)d_in[4];  const float* bxz = (const float*)d_in[5];
    const float* Whz = (const float*)d_in[6];  const float* bhz = (const float*)d_in[7];
    const float* Wxr = (const float*)d_in[8];  const float* bxr = (const float*)d_in[9];
    const float* Whr = (const float*)d_in[10]; const float* bhr = (const float*)d_in[11];
    const float* Wxh = (const float*)d_in[12]; const float* bxh = (const float*)d_in[13];
    const float* Whh = (const float*)d_in[14]; const float* bhh = (const float*)d_in[15];
    float* out = (float*)d_out;

    int N = in_sizes[0] / D;
    int E = in_sizes[2];
    int L = in_sizes[5] / D;

    const int* rowi = ei;
    const int* coli = ei + E;

    float *p_sxh, *p_P, *p_Sr, *p_Q;
    __nv_bfloat16 *p_w1h, *p_w1l, *p_w2h, *p_w2l;
    cudaGetSymbolAddress((void**)&p_sxh, g_sxh);
    cudaGetSymbolAddress((void**)&p_P,   g_P);
    cudaGetSymbolAddress((void**)&p_Sr,  g_Sr);
    cudaGetSymbolAddress((void**)&p_Q,   g_Q);
    cudaGetSymbolAddress((void**)&p_w1h, g_Wt1hi);
    cudaGetSymbolAddress((void**)&p_w1l, g_Wt1lo);
    cudaGetSymbolAddress((void**)&p_w2h, g_Wt2hi);
    cudaGetSymbolAddress((void**)&p_w2l, g_Wt2lo);

    int smem1 = 2 * (128 + 64) * (256 + 16) * 2;  // K=256
    int smem2 = 2 * (128 + 64) * (128 + 16) * 2;  // K=128
    cudaFuncSetAttribute(k_wgemm, cudaFuncAttributeMaxDynamicSharedMemorySize, smem1);

    // ---- one-time: degrees, CSR build ----
    k_deg_init<<<(N + 255) / 256, 256>>>(N);
    k_deg_edges<<<(E + 255) / 256, 256>>>(coli, ew, E);
    k_dinv<<<(N + 255) / 256, 256>>>(N);
    int nscan = (N + 1023) / 1024;
    k_scan1<<<nscan, 1024>>>(N);
    k_scan2<<<1, 64>>>(nscan);
    k_scan3<<<(N + 255) / 256, 256>>>(N);
    k_place<<<(E + 255) / 256, 256>>>(rowi, coli, ew, E);

    int nwblocks = (N * 32 + 255) / 256;  // warp per node
    int mtiles = (N + 127) / 128;

    for (int i = 0; i < L; i++) {
        const float* xin = (i == 0) ? x : out + (size_t)(i - 1) * N * D;
        const float* hi = h + (size_t)i * N * D;

        k_build_wt1<<<(384 * 256 + 255) / 256, 256>>>(Wxz + (size_t)i * D * D, Whz + (size_t)i * D * D,
                                                      Wxr + (size_t)i * D * D, Whr + (size_t)i * D * D,
                                                      Wxh + (size_t)i * D * D);
        k_build_wt2<<<(128 * 128 + 255) / 256, 256>>>(Whh + (size_t)i * D * D);
        k_prep<<<(N * 32 + 255) / 256, 256>>>(xin, hi, N);
        k_csr256<<<nwblocks, 256>>>(N);
        k_wgemm<<<mtiles, 256, smem1>>>(p_sxh, p_w1h, p_w1l, p_P, N, 256, 384, 6);
        k_gate<<<(N * 32 + 255) / 256, 256>>>(hi, bxz + i * D, bhz + i * D, bxr + i * D, bhr + i * D, N);
        k_csr128<<<nwblocks, 256>>>(N);
        k_wgemm<<<mtiles, 256, smem2>>>(p_Sr, p_w2h, p_w2l, p_Q, N, 128, 128, 2);
        k_final<<<(N * 32 + 255) / 256, 256>>>(hi, bxh + i * D, bhh + i * D, out + (size_t)i * N * D, N);
    }
}